// round 11
// baseline (speedup 1.0000x reference)
#include <cuda_runtime.h>
#include <cuda_fp16.h>
#include <math.h>
#include <stdint.h>

#define BATCH 8192
#define PIX 784
#define WIRES 10
#define DIM 1024
#define QDEPTH 20
#define NGATES (QDEPTH * WIRES)   // 200

#define KBIG 1024                 // pure fp16: A=fp16(S), B=fp16(U)
#define NBIG 1664                 // 832 j-slots x (re,im) interleaved
#define BKT  64                   // K per smem tile
#define NKT  (KBIG / BKT)         // 16

// ---------------- scratch ----------------
__device__ float2 g_gates[NGATES * 4];
__device__ __half g_As[(size_t)BATCH * KBIG];   // A' [m][k]
__device__ __half g_Bb[(size_t)KBIG * NBIG];    // B' [k][n]  (n = 2j | 2j+1 -> re|im)

// ---------------- helpers ----------------
__device__ __forceinline__ uint32_t smem_u32(const void* p) {
    uint32_t a;
    asm("{ .reg .u64 t; cvta.to.shared.u64 t, %1; cvt.u32.u64 %0, t; }" : "=r"(a) : "l"(p));
    return a;
}
__device__ __forceinline__ void cp_async16(uint32_t dst, const void* src) {
    asm volatile("cp.async.cg.shared.global [%0], [%1], 16;" :: "r"(dst), "l"(src));
}
#define CP_COMMIT() asm volatile("cp.async.commit_group;" ::: "memory")
#define CP_WAIT2()  asm volatile("cp.async.wait_group 2;" ::: "memory")

__device__ __forceinline__ void ldsm_x4(uint32_t* r, uint32_t addr) {
    asm volatile("ldmatrix.sync.aligned.m8n8.x4.shared.b16 {%0,%1,%2,%3}, [%4];"
                 : "=r"(r[0]), "=r"(r[1]), "=r"(r[2]), "=r"(r[3]) : "r"(addr));
}
__device__ __forceinline__ void ldsm_x4_t(uint32_t* r, uint32_t addr) {
    asm volatile("ldmatrix.sync.aligned.m8n8.x4.trans.shared.b16 {%0,%1,%2,%3}, [%4];"
                 : "=r"(r[0]), "=r"(r[1]), "=r"(r[2]), "=r"(r[3]) : "r"(addr));
}
__device__ __forceinline__ void mma16816(float* d, const uint32_t* a, const uint32_t* b) {
    asm volatile(
        "mma.sync.aligned.m16n8k16.row.col.f32.f16.f16.f32 "
        "{%0,%1,%2,%3}, {%4,%5,%6,%7}, {%8,%9}, {%0,%1,%2,%3};"
        : "+f"(d[0]), "+f"(d[1]), "+f"(d[2]), "+f"(d[3])
        : "r"(a[0]), "r"(a[1]), "r"(a[2]), "r"(a[3]), "r"(b[0]), "r"(b[1]));
}
__device__ __forceinline__ float2 cmul(float2 g, float2 v) {
    return make_float2(g.x * v.x - g.y * v.y, g.x * v.y + g.y * v.x);
}
__device__ __forceinline__ float2 cadd(float2 a, float2 b) {
    return make_float2(a.x + b.x, a.y + b.y);
}

// ---------------- kernel 1: Rot gates ----------------
__global__ void k_gates(const float* __restrict__ qw) {
    int g = blockIdx.x * blockDim.x + threadIdx.x;
    if (g >= NGATES) return;
    float phi = qw[g * 3 + 0], th = qw[g * 3 + 1], om = qw[g * 3 + 2];
    float c = cosf(0.5f * th), s = sinf(0.5f * th);
    float A = 0.5f * (phi + om), B = 0.5f * (phi - om);
    float cA = cosf(A), sA = sinf(A), cB = cosf(B), sB = sinf(B);
    g_gates[g * 4 + 0] = make_float2(cA * c, -sA * c);
    g_gates[g * 4 + 1] = make_float2(-cB * s, -sB * s);
    g_gates[g * 4 + 2] = make_float2(cB * s, -sB * s);
    g_gates[g * 4 + 3] = make_float2(cA * c,  sA * c);
}

// ---------------- kernel 2: fused angles + fp16 product state ----------------
__global__ __launch_bounds__(256) void k_angA(const float* __restrict__ x,
                                              const float* __restrict__ W,
                                              const float* __restrict__ bias) {
    const int warp = blockIdx.x * 8 + (threadIdx.x >> 5);
    const int lane = threadIdx.x & 31;
    const float* xr = x + (size_t)warp * PIX;
    float acc[WIRES];
#pragma unroll
    for (int w = 0; w < WIRES; w++) acc[w] = 0.f;
    for (int p = lane; p < PIX; p += 32) {
        float xv = xr[p];
#pragma unroll
        for (int w = 0; w < WIRES; w++)
            acc[w] = fmaf(xv, __ldg(&W[w * PIX + p]), acc[w]);
    }
#pragma unroll
    for (int w = 0; w < WIRES; w++) {
#pragma unroll
        for (int o = 16; o; o >>= 1)
            acc[w] += __shfl_xor_sync(0xffffffffu, acc[w], o);
    }
    float cl = 1.f, cr = 1.f;
#pragma unroll
    for (int w = 0; w < 5; w++) {
        float h = 0.5f * (acc[w] + __ldg(&bias[w]));
        float s, c; sincosf(h, &s, &c);
        cl *= ((lane >> (4 - w)) & 1) ? s : c;
    }
#pragma unroll
    for (int w = 5; w < 10; w++) {
        float h = 0.5f * (acc[w] + __ldg(&bias[w]));
        float s, c; sincosf(h, &s, &c);
        cr *= ((lane >> (9 - w)) & 1) ? s : c;
    }
    char* rowb = (char*)(g_As + (size_t)warp * KBIG) + lane * 64;
#pragma unroll
    for (int q = 0; q < 32; q += 8) {
        uint32_t u[4];
#pragma unroll
        for (int j = 0; j < 4; j++) {
            float r0 = __shfl_sync(0xffffffffu, cr, q + 2 * j);
            float r1 = __shfl_sync(0xffffffffu, cr, q + 2 * j + 1);
            __half2 h2 = __floats2half2_rn(cl * r0, cl * r1);
            u[j] = *(uint32_t*)&h2;
        }
        *(uint4*)(rowb + q * 2) = make_uint4(u[0], u[1], u[2], u[3]);
    }
}

// ---------------- kernel 3: build U, 8 amps/thread, writes B' directly -------
// 128 threads per column, 4 columns per block (512 thr). Thread owns amps
// {tc + 128q}, q=0..7. Wires 0-2 (bits 9-7) thread-local; wires 3-4 (bits 6-5)
// smem exchange; wires 5-9 (bits 4-0) shfl. CNOT ring is GF(2)-linear:
// sigma(tc ^ q<<7) = sigma(tc) ^ sigma(q<<7) (basis images precomputed per r).
#define CPB 4
#define TPC 128
#define BUILD_SMEM (2 * CPB * 1024 * 8)   // 65536 bytes, double-buffered state

__global__ __launch_bounds__(512, 2) void k_buildU() {
    extern __shared__ float2 dbuf[];      // [2][CPB][1024]
    __shared__ float2 gs[NGATES * 4];
    __shared__ int sigt[9][3];            // sigma(128/256/512) per r-1
    const int tid = threadIdx.x;
    const int tc = tid & (TPC - 1);
    const int cid = tid >> 7;
    const int lane = tid & 31;
    const int col = blockIdx.x * CPB + cid;

    for (int i = tid; i < NGATES * 4; i += 512) gs[i] = g_gates[i];
    if (tid < 27) {
        int r = tid / 3 + 1, bsel = tid % 3;
        int p = 128 << bsel;
#pragma unroll
        for (int w = 9; w >= 0; w--) {
            int cm = 1 << (9 - w);
            int tm = 1 << (9 - ((w + r) % 10));
            if (p & cm) p ^= tm;
        }
        sigt[tid / 3][bsel] = p;
    }
    float2 s[8];
#pragma unroll
    for (int q = 0; q < 8; q++)
        s[q] = make_float2((tc + (q << 7)) == col ? 1.f : 0.f, 0.f);
    __syncthreads();

    int pb = 0;
    for (int l = 0; l < QDEPTH; l++) {
        const float2* gl = &gs[l * WIRES * 4];
        // wires 0..2: thread-local (amp bit 9-w = q bit 2-w)
#pragma unroll
        for (int w = 0; w <= 2; w++) {
            const float2 g00 = gl[w * 4], g01 = gl[w * 4 + 1];
            const float2 g10 = gl[w * 4 + 2], g11 = gl[w * 4 + 3];
            const int qd = 4 >> w;
#pragma unroll
            for (int q = 0; q < 8; q++) {
                if (!(q & qd)) {
                    float2 a0 = s[q], a1 = s[q + qd];
                    s[q]      = cadd(cmul(g00, a0), cmul(g01, a1));
                    s[q + qd] = cadd(cmul(g10, a0), cmul(g11, a1));
                }
            }
        }
        // wires 3..4: smem exchange (amp bit 6 / 5 = tc bit 6 / 5)
#pragma unroll
        for (int w = 3; w <= 4; w++) {
            const float2 g00 = gl[w * 4], g01 = gl[w * 4 + 1];
            const float2 g10 = gl[w * 4 + 2], g11 = gl[w * 4 + 3];
            const int b = 9 - w;
            const int d = 1 << b;
            float2* base = dbuf + (pb * CPB + cid) * 1024;
#pragma unroll
            for (int q = 0; q < 8; q++) base[tc + (q << 7)] = s[q];
            __syncthreads();
            const int pt = tc ^ d;
            if ((tc >> b) & 1) {
#pragma unroll
                for (int q = 0; q < 8; q++) {
                    float2 p = base[pt + (q << 7)];
                    s[q] = cadd(cmul(g10, p), cmul(g11, s[q]));
                }
            } else {
#pragma unroll
                for (int q = 0; q < 8; q++) {
                    float2 p = base[pt + (q << 7)];
                    s[q] = cadd(cmul(g00, s[q]), cmul(g01, p));
                }
            }
            pb ^= 1;
        }
        // wires 5..9: shfl (amp bit 4..0 = lane bit)
#pragma unroll
        for (int w = 5; w <= 9; w++) {
            const float2 g00 = gl[w * 4], g01 = gl[w * 4 + 1];
            const float2 g10 = gl[w * 4 + 2], g11 = gl[w * 4 + 3];
            const int b = 9 - w;
            const int d = 1 << b;
            const int hi = (lane >> b) & 1;
#pragma unroll
            for (int q = 0; q < 8; q++) {
                float2 p;
                p.x = __shfl_xor_sync(0xffffffffu, s[q].x, d);
                p.y = __shfl_xor_sync(0xffffffffu, s[q].y, d);
                s[q] = hi ? cadd(cmul(g10, p), cmul(g11, s[q]))
                          : cadd(cmul(g00, s[q]), cmul(g01, p));
            }
        }
        // CNOT ring: gather via linear sigma
        const int ri = l % 9;
        const int r = ri + 1;
        float2* base = dbuf + (pb * CPB + cid) * 1024;
#pragma unroll
        for (int q = 0; q < 8; q++) base[tc + (q << 7)] = s[q];
        __syncthreads();
        int st = tc;
#pragma unroll
        for (int w = 9; w >= 0; w--) {
            int cm = 1 << (9 - w);
            int tm = 1 << (9 - ((w + r) % 10));
            if (st & cm) st ^= tm;
        }
        const int s7 = sigt[ri][0], s8 = sigt[ri][1], s9 = sigt[ri][2];
#pragma unroll
        for (int q = 0; q < 8; q++) {
            int idx = st ^ ((q & 1) ? s7 : 0) ^ ((q & 2) ? s8 : 0) ^ ((q & 4) ? s9 : 0);
            s[q] = base[idx];
        }
        pb ^= 1;
    }
    // store B'[k=col][n=2j|2j+1] = (re, im)
    __half2* brow = (__half2*)(g_Bb + (size_t)col * NBIG);
#pragma unroll
    for (int q = 0; q < 8; q++) {
        int amp = tc + (q << 7);
        if (amp < NBIG / 2) brow[amp] = __floats2half2_rn(s[q].x, s[q].y);
    }
}

// ---------------- kernel 4: mma.sync fp16 GEMM + epilogue ----------------
// BM=128, BN=128, BK=64, 3-stage cp.async, 8 warps (2 M x 4 N), warp tile 64x32.
#define STAGE_BYTES 32768
#define GEMM_SMEM   (3 * STAGE_BYTES)   // 98304

__device__ __forceinline__ void load_tile(uint32_t sbase, int stage, int kt,
                                          const __half* gA,
                                          const __half* gB, int tid) {
    const uint32_t aS = sbase + stage * STAGE_BYTES;
    const uint32_t bS = aS + 16384;
    {
        const int r0 = tid >> 3;
        const int c  = tid & 7;
        const uint32_t cx = (uint32_t)(c * 16);
#pragma unroll
        for (int p = 0; p < 4; p++) {
            const int row = p * 32 + r0;
            const uint32_t off = (uint32_t)(row * 128) + (cx ^ ((row & 7) * 16));
            cp_async16(aS + off, gA + (size_t)row * KBIG + (size_t)kt * BKT + c * 8);
        }
    }
    {
        const int r = tid >> 2;
        const int cq = (tid & 3) * 4;
        const __half* gsrc = gB + (size_t)(kt * BKT + r) * NBIG + cq * 8;
        const uint32_t rbase = bS + (uint32_t)(r * 256);
        const uint32_t rs = (uint32_t)((r & 7) * 16);
#pragma unroll
        for (int q = 0; q < 4; q++) {
            const uint32_t off = ((uint32_t)((cq + q) * 16)) ^ rs;
            cp_async16(rbase + off, gsrc + q * 8);
        }
    }
}

__global__ __launch_bounds__(256, 2) void k_gemm(float* __restrict__ out) {
    extern __shared__ char smem[];
    const uint32_t sbase = smem_u32(smem);
    const int tid = threadIdx.x;
    const int wid = tid >> 5, lane = tid & 31;
    const int wm = wid & 1, wn = wid >> 1;      // 2 x 4 warp grid
    const int m0 = blockIdx.x * 128;
    const int n0 = blockIdx.y * 128;

    const __half* gA = g_As + (size_t)m0 * KBIG;
    const __half* gB = g_Bb + n0;

    float acc[4][4][4];
#pragma unroll
    for (int i = 0; i < 4; i++)
#pragma unroll
        for (int j = 0; j < 4; j++)
#pragma unroll
            for (int q = 0; q < 4; q++) acc[i][j][q] = 0.f;

    load_tile(sbase, 0, 0, gA, gB, tid); CP_COMMIT();
    load_tile(sbase, 1, 1, gA, gB, tid); CP_COMMIT();

    const int a_row = wm * 64 + (lane & 7) + ((lane >> 3) & 1) * 8;
    const uint32_t a_kx = ((lane >> 4) & 1) * 16;
    const int b_kr = (lane & 7) + ((lane >> 3) & 1) * 8;
    const int b_ch = wn * 4 + ((lane >> 4) & 1);

    int stage = 0;
    for (int kt = 0; kt < NKT; kt++) {
        if (kt + 2 < NKT) load_tile(sbase, (stage + 2) % 3, kt + 2, gA, gB, tid);
        CP_COMMIT();
        CP_WAIT2();
        __syncthreads();

        const uint32_t aS = sbase + stage * STAGE_BYTES;
        const uint32_t bS = aS + 16384;
#pragma unroll
        for (int ks = 0; ks < 4; ks++) {
            uint32_t afr[4][4], bfr[2][4];
#pragma unroll
            for (int mf = 0; mf < 4; mf++) {
                const int row = a_row + mf * 16;
                const uint32_t kb = (uint32_t)(ks * 32) + a_kx;
                ldsm_x4(afr[mf], aS + (uint32_t)(row * 128) + (kb ^ ((row & 7) * 16)));
            }
#pragma unroll
            for (int nf2 = 0; nf2 < 2; nf2++) {
                const int krow = ks * 16 + b_kr;
                const int ch = b_ch + nf2 * 2;
                ldsm_x4_t(bfr[nf2], bS + (uint32_t)(krow * 256) +
                                    (((uint32_t)(ch * 16)) ^ ((krow & 7) * 16)));
            }
#pragma unroll
            for (int mf = 0; mf < 4; mf++)
#pragma unroll
                for (int nf = 0; nf < 4; nf++)
                    mma16816(acc[mf][nf], afr[mf], &bfr[nf >> 1][(nf & 1) * 2]);
        }
        __syncthreads();
        stage = (stage + 1) % 3;
    }

    const int jbase = (n0 >> 1) + wn * 16;
    const int rbase = m0 + wm * 64 + (lane >> 2);
    const int jq = lane & 3;
#pragma unroll
    for (int mf = 0; mf < 4; mf++) {
#pragma unroll
        for (int nf = 0; nf < 4; nf++) {
            const int j = jbase + nf * 4 + jq;
            if (j < PIX) {
                const float re0 = acc[mf][nf][0], im0 = acc[mf][nf][1];
                const float re1 = acc[mf][nf][2], im1 = acc[mf][nf][3];
                out[(size_t)(rbase + mf * 16) * PIX + j] =
                    fminf((re0 * re0 + im0 * im0) * (float)PIX, 1.0f);
                out[(size_t)(rbase + mf * 16 + 8) * PIX + j] =
                    fminf((re1 * re1 + im1 * im1) * (float)PIX, 1.0f);
            }
        }
    }
}

// ---------------- launch ----------------
extern "C" void kernel_launch(void* const* d_in, const int* in_sizes, int n_in,
                              void* d_out, int out_size) {
    const float* x  = (const float*)d_in[0];
    const float* W  = (const float*)d_in[1];
    const float* b  = (const float*)d_in[2];
    const float* qw = (const float*)d_in[3];
    float* out = (float*)d_out;

    cudaFuncSetAttribute(k_gemm, cudaFuncAttributeMaxDynamicSharedMemorySize, GEMM_SMEM);
    cudaFuncSetAttribute(k_buildU, cudaFuncAttributeMaxDynamicSharedMemorySize, BUILD_SMEM);

    k_gates<<<1, 256>>>(qw);                       // launch 1
    k_angA<<<BATCH / 8, 256>>>(x, W, b);           // launch 2
    k_buildU<<<DIM / CPB, 512, BUILD_SMEM>>>();    // launch 3
    dim3 gg(BATCH / 128, NBIG / 128);              // 64 x 13
    k_gemm<<<gg, 256, GEMM_SMEM>>>(out);           // launch 4
}

// round 13
// speedup vs baseline: 1.0346x; 1.0346x over previous
#include <cuda_runtime.h>
#include <cuda_fp16.h>
#include <math.h>
#include <stdint.h>

#define BATCH 8192
#define PIX 784
#define WIRES 10
#define DIM 1024
#define QDEPTH 20
#define NGATES (QDEPTH * WIRES)   // 200

#define KBIG 1024                 // pure fp16: A=fp16(S), B=fp16(U)
#define NBIG 1664                 // 832 j-slots x (re,im) interleaved
#define BKT  64                   // K per smem tile
#define NKT  (KBIG / BKT)         // 16

// ---------------- scratch ----------------
__device__ float2 g_gates[NGATES * 4];
__device__ __half g_As[(size_t)BATCH * KBIG];   // A' [m][k]
__device__ __half g_Bk[(size_t)KBIG * NBIG];    // buildU out: [k][n]
__device__ __half g_Bb[(size_t)NBIG * KBIG];    // GEMM B: [n][k]

// ---------------- helpers ----------------
__device__ __forceinline__ uint32_t smem_u32(const void* p) {
    uint32_t a;
    asm("{ .reg .u64 t; cvta.to.shared.u64 t, %1; cvt.u32.u64 %0, t; }" : "=r"(a) : "l"(p));
    return a;
}
__device__ __forceinline__ void cp_async16(uint32_t dst, const void* src) {
    asm volatile("cp.async.cg.shared.global [%0], [%1], 16;" :: "r"(dst), "l"(src));
}
#define CP_COMMIT() asm volatile("cp.async.commit_group;" ::: "memory")
#define CP_WAIT2()  asm volatile("cp.async.wait_group 2;" ::: "memory")

__device__ __forceinline__ void ldsm_x4(uint32_t* r, uint32_t addr) {
    asm volatile("ldmatrix.sync.aligned.m8n8.x4.shared.b16 {%0,%1,%2,%3}, [%4];"
                 : "=r"(r[0]), "=r"(r[1]), "=r"(r[2]), "=r"(r[3]) : "r"(addr));
}
__device__ __forceinline__ void mma16816(float* d, const uint32_t* a, const uint32_t* b) {
    asm volatile(
        "mma.sync.aligned.m16n8k16.row.col.f32.f16.f16.f32 "
        "{%0,%1,%2,%3}, {%4,%5,%6,%7}, {%8,%9}, {%0,%1,%2,%3};"
        : "+f"(d[0]), "+f"(d[1]), "+f"(d[2]), "+f"(d[3])
        : "r"(a[0]), "r"(a[1]), "r"(a[2]), "r"(a[3]), "r"(b[0]), "r"(b[1]));
}
__device__ __forceinline__ float2 cmul(float2 g, float2 v) {
    return make_float2(g.x * v.x - g.y * v.y, g.x * v.y + g.y * v.x);
}
__device__ __forceinline__ float2 cadd(float2 a, float2 b) {
    return make_float2(a.x + b.x, a.y + b.y);
}

// ---------------- kernel: Rot gates ----------------
__global__ void k_gates(const float* __restrict__ qw) {
    int g = blockIdx.x * blockDim.x + threadIdx.x;
    if (g >= NGATES) return;
    float phi = qw[g * 3 + 0], th = qw[g * 3 + 1], om = qw[g * 3 + 2];
    float c = cosf(0.5f * th), s = sinf(0.5f * th);
    float A = 0.5f * (phi + om), B = 0.5f * (phi - om);
    float cA = cosf(A), sA = sinf(A), cB = cosf(B), sB = sinf(B);
    g_gates[g * 4 + 0] = make_float2(cA * c, -sA * c);
    g_gates[g * 4 + 1] = make_float2(-cB * s, -sB * s);
    g_gates[g * 4 + 2] = make_float2(cB * s, -sB * s);
    g_gates[g * 4 + 3] = make_float2(cA * c,  sA * c);
}

// ---------------- kernel: fused angles + fp16 product state (float4 loads) ---
__global__ __launch_bounds__(256) void k_angA(const float* __restrict__ x,
                                              const float* __restrict__ W,
                                              const float* __restrict__ bias,
                                              int base) {
    const int warp = base + blockIdx.x * 8 + (threadIdx.x >> 5);
    const int lane = threadIdx.x & 31;
    const float4* xr4 = (const float4*)(x + (size_t)warp * PIX);
    float acc[WIRES];
#pragma unroll
    for (int w = 0; w < WIRES; w++) acc[w] = 0.f;
    // 196 float4 per row; lanes stride 32
    for (int p4 = lane; p4 < PIX / 4; p4 += 32) {
        const float4 xv = xr4[p4];
#pragma unroll
        for (int w = 0; w < WIRES; w++) {
            const float4 wv = __ldg((const float4*)(W + w * PIX) + p4);
            acc[w] = fmaf(xv.x, wv.x, acc[w]);
            acc[w] = fmaf(xv.y, wv.y, acc[w]);
            acc[w] = fmaf(xv.z, wv.z, acc[w]);
            acc[w] = fmaf(xv.w, wv.w, acc[w]);
        }
    }
#pragma unroll
    for (int w = 0; w < WIRES; w++) {
#pragma unroll
        for (int o = 16; o; o >>= 1)
            acc[w] += __shfl_xor_sync(0xffffffffu, acc[w], o);
    }
    float cl = 1.f, cr = 1.f;
#pragma unroll
    for (int w = 0; w < 5; w++) {
        float h = 0.5f * (acc[w] + __ldg(&bias[w]));
        float s, c; sincosf(h, &s, &c);
        cl *= ((lane >> (4 - w)) & 1) ? s : c;
    }
#pragma unroll
    for (int w = 5; w < 10; w++) {
        float h = 0.5f * (acc[w] + __ldg(&bias[w]));
        float s, c; sincosf(h, &s, &c);
        cr *= ((lane >> (9 - w)) & 1) ? s : c;
    }
    char* rowb = (char*)(g_As + (size_t)warp * KBIG) + lane * 64;
#pragma unroll
    for (int q = 0; q < 32; q += 8) {
        uint32_t u[4];
#pragma unroll
        for (int j = 0; j < 4; j++) {
            float r0 = __shfl_sync(0xffffffffu, cr, q + 2 * j);
            float r1 = __shfl_sync(0xffffffffu, cr, q + 2 * j + 1);
            __half2 h2 = __floats2half2_rn(cl * r0, cl * r1);
            u[j] = *(uint32_t*)&h2;
        }
        *(uint4*)(rowb + q * 2) = make_uint4(u[0], u[1], u[2], u[3]);
    }
}

// ---------------- kernel: build U, 8 amps/thread, writes [k][n] --------------
#define CPB 4
#define TPC 128
#define BUILD_SMEM (2 * CPB * 1024 * 8)   // 65536 bytes

__global__ __launch_bounds__(512, 2) void k_buildU() {
    extern __shared__ float2 dbuf[];      // [2][CPB][1024]
    __shared__ float2 gs[NGATES * 4];
    __shared__ int sigt[9][3];
    const int tid = threadIdx.x;
    const int tc = tid & (TPC - 1);
    const int cid = tid >> 7;
    const int lane = tid & 31;
    const int col = blockIdx.x * CPB + cid;

    for (int i = tid; i < NGATES * 4; i += 512) gs[i] = g_gates[i];
    if (tid < 27) {
        int r = tid / 3 + 1, bsel = tid % 3;
        int p = 128 << bsel;
#pragma unroll
        for (int w = 9; w >= 0; w--) {
            int cm = 1 << (9 - w);
            int tm = 1 << (9 - ((w + r) % 10));
            if (p & cm) p ^= tm;
        }
        sigt[tid / 3][bsel] = p;
    }
    float2 s[8];
#pragma unroll
    for (int q = 0; q < 8; q++)
        s[q] = make_float2((tc + (q << 7)) == col ? 1.f : 0.f, 0.f);
    __syncthreads();

    int pb = 0;
    for (int l = 0; l < QDEPTH; l++) {
        const float2* gl = &gs[l * WIRES * 4];
#pragma unroll
        for (int w = 0; w <= 2; w++) {
            const float2 g00 = gl[w * 4], g01 = gl[w * 4 + 1];
            const float2 g10 = gl[w * 4 + 2], g11 = gl[w * 4 + 3];
            const int qd = 4 >> w;
#pragma unroll
            for (int q = 0; q < 8; q++) {
                if (!(q & qd)) {
                    float2 a0 = s[q], a1 = s[q + qd];
                    s[q]      = cadd(cmul(g00, a0), cmul(g01, a1));
                    s[q + qd] = cadd(cmul(g10, a0), cmul(g11, a1));
                }
            }
        }
#pragma unroll
        for (int w = 3; w <= 4; w++) {
            const float2 g00 = gl[w * 4], g01 = gl[w * 4 + 1];
            const float2 g10 = gl[w * 4 + 2], g11 = gl[w * 4 + 3];
            const int b = 9 - w;
            const int d = 1 << b;
            float2* base = dbuf + (pb * CPB + cid) * 1024;
#pragma unroll
            for (int q = 0; q < 8; q++) base[tc + (q << 7)] = s[q];
            __syncthreads();
            const int pt = tc ^ d;
            if ((tc >> b) & 1) {
#pragma unroll
                for (int q = 0; q < 8; q++) {
                    float2 p = base[pt + (q << 7)];
                    s[q] = cadd(cmul(g10, p), cmul(g11, s[q]));
                }
            } else {
#pragma unroll
                for (int q = 0; q < 8; q++) {
                    float2 p = base[pt + (q << 7)];
                    s[q] = cadd(cmul(g00, s[q]), cmul(g01, p));
                }
            }
            pb ^= 1;
        }
#pragma unroll
        for (int w = 5; w <= 9; w++) {
            const float2 g00 = gl[w * 4], g01 = gl[w * 4 + 1];
            const float2 g10 = gl[w * 4 + 2], g11 = gl[w * 4 + 3];
            const int b = 9 - w;
            const int d = 1 << b;
            const int hi = (lane >> b) & 1;
#pragma unroll
            for (int q = 0; q < 8; q++) {
                float2 p;
                p.x = __shfl_xor_sync(0xffffffffu, s[q].x, d);
                p.y = __shfl_xor_sync(0xffffffffu, s[q].y, d);
                s[q] = hi ? cadd(cmul(g10, p), cmul(g11, s[q]))
                          : cadd(cmul(g00, s[q]), cmul(g01, p));
            }
        }
        const int ri = l % 9;
        const int r = ri + 1;
        float2* base = dbuf + (pb * CPB + cid) * 1024;
#pragma unroll
        for (int q = 0; q < 8; q++) base[tc + (q << 7)] = s[q];
        __syncthreads();
        int st = tc;
#pragma unroll
        for (int w = 9; w >= 0; w--) {
            int cm = 1 << (9 - w);
            int tm = 1 << (9 - ((w + r) % 10));
            if (st & cm) st ^= tm;
        }
        const int s7 = sigt[ri][0], s8 = sigt[ri][1], s9 = sigt[ri][2];
#pragma unroll
        for (int q = 0; q < 8; q++) {
            int idx = st ^ ((q & 1) ? s7 : 0) ^ ((q & 2) ? s8 : 0) ^ ((q & 4) ? s9 : 0);
            s[q] = base[idx];
        }
        pb ^= 1;
    }
    __half2* brow = (__half2*)(g_Bk + (size_t)col * NBIG);
#pragma unroll
    for (int q = 0; q < 8; q++) {
        int amp = tc + (q << 7);
        if (amp < NBIG / 2) brow[amp] = __floats2half2_rn(s[q].x, s[q].y);
    }
}

// ---------------- kernel: B2 = fp16 transpose [k][n] -> [n][k] ---------------
__global__ void k_B2() {
    __shared__ __half tile[32][34];
    const int n0 = blockIdx.x * 32, k0 = blockIdx.y * 32;
    const int tx = threadIdx.x, ty = threadIdx.y;
    for (int r = ty; r < 32; r += 8)
        tile[r][tx] = g_Bk[(size_t)(k0 + r) * NBIG + n0 + tx];
    __syncthreads();
    for (int jl = ty; jl < 32; jl += 8)
        g_Bb[(size_t)(n0 + jl) * KBIG + k0 + tx] = tile[tx][jl];
}

// ---------------- kernel: mma.sync fp16 GEMM + epilogue (R9 layout) ----------
#define STAGE_BYTES 32768
#define GEMM_SMEM   (3 * STAGE_BYTES)   // 98304

__device__ __forceinline__ void load_tile(uint32_t sbase, int stage, int kt,
                                          const __half* gA,
                                          const __half* gB, int tid) {
    const uint32_t aS = sbase + stage * STAGE_BYTES;
    const uint32_t bS = aS + 16384;
    const int r0 = tid >> 3;
    const int c  = tid & 7;
    const uint32_t cx = (uint32_t)(c * 16);
#pragma unroll
    for (int p = 0; p < 4; p++) {
        const int row = p * 32 + r0;
        const uint32_t off = (uint32_t)(row * 128) + (cx ^ ((row & 7) * 16));
        cp_async16(aS + off, gA + (size_t)row * KBIG + (size_t)kt * BKT + c * 8);
    }
#pragma unroll
    for (int p = 0; p < 4; p++) {
        const int row = p * 32 + r0;
        const uint32_t off = (uint32_t)(row * 128) + (cx ^ ((row & 7) * 16));
        cp_async16(bS + off, gB + (size_t)row * KBIG + (size_t)kt * BKT + c * 8);
    }
}

__global__ __launch_bounds__(256, 2) void k_gemm(float* __restrict__ out) {
    extern __shared__ char smem[];
    const uint32_t sbase = smem_u32(smem);
    const int tid = threadIdx.x;
    const int wid = tid >> 5, lane = tid & 31;
    const int wm = wid & 1, wn = wid >> 1;      // 2 x 4 warp grid
    const int m0 = blockIdx.x * 128;
    const int n0 = blockIdx.y * 128;

    const __half* gA = g_As + (size_t)m0 * KBIG;
    const __half* gB = g_Bb + (size_t)n0 * KBIG;

    float acc[4][4][4];
#pragma unroll
    for (int i = 0; i < 4; i++)
#pragma unroll
        for (int j = 0; j < 4; j++)
#pragma unroll
            for (int q = 0; q < 4; q++) acc[i][j][q] = 0.f;

    load_tile(sbase, 0, 0, gA, gB, tid); CP_COMMIT();
    load_tile(sbase, 1, 1, gA, gB, tid); CP_COMMIT();

    const int a_row = wm * 64 + (lane & 7) + ((lane >> 3) & 1) * 8;
    const uint32_t a_kx = ((lane >> 4) & 1) * 16;
    const int b_row = wn * 32 + (lane & 7) + ((lane >> 4) & 1) * 8;
    const uint32_t b_kx = ((lane >> 3) & 1) * 16;

    int stage = 0;
    for (int kt = 0; kt < NKT; kt++) {
        if (kt + 2 < NKT) load_tile(sbase, (stage + 2) % 3, kt + 2, gA, gB, tid);
        CP_COMMIT();
        CP_WAIT2();
        __syncthreads();

        const uint32_t aS = sbase + stage * STAGE_BYTES;
        const uint32_t bS = aS + 16384;
#pragma unroll
        for (int ks = 0; ks < 4; ks++) {
            uint32_t afr[4][4], bfr[2][4];
#pragma unroll
            for (int mf = 0; mf < 4; mf++) {
                const int row = a_row + mf * 16;
                const uint32_t kb = (uint32_t)(ks * 32) + a_kx;
                ldsm_x4(afr[mf], aS + (uint32_t)(row * 128) + (kb ^ ((row & 7) * 16)));
            }
#pragma unroll
            for (int nf2 = 0; nf2 < 2; nf2++) {
                const int row = b_row + nf2 * 16;
                const uint32_t kb = (uint32_t)(ks * 32) + b_kx;
                ldsm_x4(bfr[nf2], bS + (uint32_t)(row * 128) + (kb ^ ((row & 7) * 16)));
            }
#pragma unroll
            for (int mf = 0; mf < 4; mf++)
#pragma unroll
                for (int nf = 0; nf < 4; nf++)
                    mma16816(acc[mf][nf], afr[mf], &bfr[nf >> 1][(nf & 1) * 2]);
        }
        __syncthreads();
        stage = (stage + 1) % 3;
    }

    const int jbase = (n0 >> 1) + wn * 16;
    const int rbase = m0 + wm * 64 + (lane >> 2);
    const int jq = lane & 3;
#pragma unroll
    for (int mf = 0; mf < 4; mf++) {
#pragma unroll
        for (int nf = 0; nf < 4; nf++) {
            const int j = jbase + nf * 4 + jq;
            if (j < PIX) {
                const float re0 = acc[mf][nf][0], im0 = acc[mf][nf][1];
                const float re1 = acc[mf][nf][2], im1 = acc[mf][nf][3];
                out[(size_t)(rbase + mf * 16) * PIX + j] =
                    fminf((re0 * re0 + im0 * im0) * (float)PIX, 1.0f);
                out[(size_t)(rbase + mf * 16 + 8) * PIX + j] =
                    fminf((re1 * re1 + im1 * im1) * (float)PIX, 1.0f);
            }
        }
    }
}

// ---------------- launch ----------------
extern "C" void kernel_launch(void* const* d_in, const int* in_sizes, int n_in,
                              void* d_out, int out_size) {
    const float* x  = (const float*)d_in[0];
    const float* W  = (const float*)d_in[1];
    const float* b  = (const float*)d_in[2];
    const float* qw = (const float*)d_in[3];
    float* out = (float*)d_out;

    cudaFuncSetAttribute(k_gemm, cudaFuncAttributeMaxDynamicSharedMemorySize, GEMM_SMEM);
    cudaFuncSetAttribute(k_buildU, cudaFuncAttributeMaxDynamicSharedMemorySize, BUILD_SMEM);

    k_angA<<<BATCH / 16, 256>>>(x, W, b, 0);             // launch 1
    k_angA<<<BATCH / 16, 256>>>(x, W, b, BATCH / 2);     // launch 2
    k_gates<<<1, 256>>>(qw);                             // launch 3
    k_buildU<<<DIM / CPB, 512, BUILD_SMEM>>>();          // launch 4 (profiled)
    dim3 gt(NBIG / 32, KBIG / 32);
    k_B2<<<gt, dim3(32, 8)>>>();                         // launch 5
    dim3 gg(BATCH / 128, NBIG / 128);                    // 64 x 13
    k_gemm<<<gg, 256, GEMM_SMEM>>>(out);                 // launch 6
}

// round 14
// speedup vs baseline: 1.4576x; 1.4088x over previous
#include <cuda_runtime.h>
#include <cuda_fp16.h>
#include <math.h>
#include <stdint.h>

#define BATCH 8192
#define PIX 784
#define WIRES 10
#define DIM 1024
#define QDEPTH 20
#define NGATES (QDEPTH * WIRES)   // 200

#define KBIG 1024                 // pure fp16: A=fp16(S), B=fp16(U)
#define NBIG 1664                 // 832 j-slots x (re,im) interleaved
#define NJ   (NBIG / 2)           // 832 rows of U actually needed
#define BKT  64                   // K per smem tile
#define NKT  (KBIG / BKT)         // 16

// ---------------- scratch ----------------
__device__ float2 g_gates[NGATES * 4];          // ADJOINT Rot gates
__device__ __half g_As[(size_t)BATCH * KBIG];   // A' [m][k]
__device__ __half g_Bb[(size_t)NBIG * KBIG];    // GEMM B: [n][k]

// ---------------- helpers ----------------
__device__ __forceinline__ uint32_t smem_u32(const void* p) {
    uint32_t a;
    asm("{ .reg .u64 t; cvta.to.shared.u64 t, %1; cvt.u32.u64 %0, t; }" : "=r"(a) : "l"(p));
    return a;
}
__device__ __forceinline__ void cp_async16(uint32_t dst, const void* src) {
    asm volatile("cp.async.cg.shared.global [%0], [%1], 16;" :: "r"(dst), "l"(src));
}
#define CP_COMMIT() asm volatile("cp.async.commit_group;" ::: "memory")
#define CP_WAIT2()  asm volatile("cp.async.wait_group 2;" ::: "memory")

__device__ __forceinline__ void ldsm_x4(uint32_t* r, uint32_t addr) {
    asm volatile("ldmatrix.sync.aligned.m8n8.x4.shared.b16 {%0,%1,%2,%3}, [%4];"
                 : "=r"(r[0]), "=r"(r[1]), "=r"(r[2]), "=r"(r[3]) : "r"(addr));
}
__device__ __forceinline__ void mma16816(float* d, const uint32_t* a, const uint32_t* b) {
    asm volatile(
        "mma.sync.aligned.m16n8k16.row.col.f32.f16.f16.f32 "
        "{%0,%1,%2,%3}, {%4,%5,%6,%7}, {%8,%9}, {%0,%1,%2,%3};"
        : "+f"(d[0]), "+f"(d[1]), "+f"(d[2]), "+f"(d[3])
        : "r"(a[0]), "r"(a[1]), "r"(a[2]), "r"(a[3]), "r"(b[0]), "r"(b[1]));
}
__device__ __forceinline__ float2 cmul(float2 g, float2 v) {
    return make_float2(g.x * v.x - g.y * v.y, g.x * v.y + g.y * v.x);
}
__device__ __forceinline__ float2 cadd(float2 a, float2 b) {
    return make_float2(a.x + b.x, a.y + b.y);
}

// ---------------- kernel: ADJOINT Rot gates ----------------
// forward Rot: m00=e^{-iA}c, m01=-e^{iB}s, m10=e^{-iB}s, m11=e^{iA}c
// adjoint:     a00=conj(m00), a01=conj(m10), a10=conj(m01), a11=conj(m11)
__global__ void k_gates(const float* __restrict__ qw) {
    int g = blockIdx.x * blockDim.x + threadIdx.x;
    if (g >= NGATES) return;
    float phi = qw[g * 3 + 0], th = qw[g * 3 + 1], om = qw[g * 3 + 2];
    float c = cosf(0.5f * th), s = sinf(0.5f * th);
    float A = 0.5f * (phi + om), B = 0.5f * (phi - om);
    float cA = cosf(A), sA = sinf(A), cB = cosf(B), sB = sinf(B);
    g_gates[g * 4 + 0] = make_float2(cA * c,  sA * c);    // conj(m00)
    g_gates[g * 4 + 1] = make_float2(cB * s,  sB * s);    // conj(m10)
    g_gates[g * 4 + 2] = make_float2(-cB * s, sB * s);    // conj(m01)
    g_gates[g * 4 + 3] = make_float2(cA * c, -sA * c);    // conj(m11)
}

// ---------------- kernel: fused angles + fp16 product state (float4 loads) ---
__global__ __launch_bounds__(256) void k_angA(const float* __restrict__ x,
                                              const float* __restrict__ W,
                                              const float* __restrict__ bias) {
    const int warp = blockIdx.x * 8 + (threadIdx.x >> 5);
    const int lane = threadIdx.x & 31;
    const float4* xr4 = (const float4*)(x + (size_t)warp * PIX);
    float acc[WIRES];
#pragma unroll
    for (int w = 0; w < WIRES; w++) acc[w] = 0.f;
    for (int p4 = lane; p4 < PIX / 4; p4 += 32) {
        const float4 xv = xr4[p4];
#pragma unroll
        for (int w = 0; w < WIRES; w++) {
            const float4 wv = __ldg((const float4*)(W + w * PIX) + p4);
            acc[w] = fmaf(xv.x, wv.x, acc[w]);
            acc[w] = fmaf(xv.y, wv.y, acc[w]);
            acc[w] = fmaf(xv.z, wv.z, acc[w]);
            acc[w] = fmaf(xv.w, wv.w, acc[w]);
        }
    }
#pragma unroll
    for (int w = 0; w < WIRES; w++) {
#pragma unroll
        for (int o = 16; o; o >>= 1)
            acc[w] += __shfl_xor_sync(0xffffffffu, acc[w], o);
    }
    float cl = 1.f, cr = 1.f;
#pragma unroll
    for (int w = 0; w < 5; w++) {
        float h = 0.5f * (acc[w] + __ldg(&bias[w]));
        float s, c; sincosf(h, &s, &c);
        cl *= ((lane >> (4 - w)) & 1) ? s : c;
    }
#pragma unroll
    for (int w = 5; w < 10; w++) {
        float h = 0.5f * (acc[w] + __ldg(&bias[w]));
        float s, c; sincosf(h, &s, &c);
        cr *= ((lane >> (9 - w)) & 1) ? s : c;
    }
    char* rowb = (char*)(g_As + (size_t)warp * KBIG) + lane * 64;
#pragma unroll
    for (int q = 0; q < 32; q += 8) {
        uint32_t u[4];
#pragma unroll
        for (int j = 0; j < 4; j++) {
            float r0 = __shfl_sync(0xffffffffu, cr, q + 2 * j);
            float r1 = __shfl_sync(0xffffffffu, cr, q + 2 * j + 1);
            __half2 h2 = __floats2half2_rn(cl * r0, cl * r1);
            u[j] = *(uint32_t*)&h2;
        }
        *(uint4*)(rowb + q * 2) = make_uint4(u[0], u[1], u[2], u[3]);
    }
}

// ---------------- kernel: INVERSE circuit on 832 basis rows ------------------
// v_j = U^dagger e_j  =>  U[j,k] = conj(v_j[k]).  For l = 19..0:
//   apply inverse CNOT ring (gather with ASCENDING composition), then Rot^dagger.
// Thread owns amps {tc + 128q} of column j. Writes B'[2j][k]=v.x, B'[2j+1][k]=-v.y.
#define CPB 4
#define TPC 128
#define BUILD_SMEM (2 * CPB * 1024 * 8)   // 65536 bytes

__global__ __launch_bounds__(512, 2) void k_buildU() {
    extern __shared__ float2 dbuf[];      // [2][CPB][1024]
    __shared__ float2 gs[NGATES * 4];
    __shared__ int sigt[9][3];            // inverse-ring images of 128/256/512
    const int tid = threadIdx.x;
    const int tc = tid & (TPC - 1);
    const int cid = tid >> 7;
    const int lane = tid & 31;
    const int col = blockIdx.x * CPB + cid;   // j in [0, 832)

    for (int i = tid; i < NGATES * 4; i += 512) gs[i] = g_gates[i];
    if (tid < 27) {
        int r = tid / 3 + 1, bsel = tid % 3;
        int p = 128 << bsel;
#pragma unroll
        for (int w = 0; w <= 9; w++) {          // ASCENDING = inverse ring
            int cm = 1 << (9 - w);
            int tm = 1 << (9 - ((w + r) % 10));
            if (p & cm) p ^= tm;
        }
        sigt[tid / 3][bsel] = p;
    }
    float2 s[8];
#pragma unroll
    for (int q = 0; q < 8; q++)
        s[q] = make_float2((tc + (q << 7)) == col ? 1.f : 0.f, 0.f);
    __syncthreads();

    int pb = 0;
    for (int ll = 0; ll < QDEPTH; ll++) {
        const int l = QDEPTH - 1 - ll;
        const float2* gl = &gs[l * WIRES * 4];

        // ---- inverse CNOT ring first ----
        {
            const int ri = l % 9;
            const int r = ri + 1;
            float2* base = dbuf + (pb * CPB + cid) * 1024;
#pragma unroll
            for (int q = 0; q < 8; q++) base[tc + (q << 7)] = s[q];
            __syncthreads();
            int st = tc;
#pragma unroll
            for (int w = 0; w <= 9; w++) {      // ASCENDING composition
                int cm = 1 << (9 - w);
                int tm = 1 << (9 - ((w + r) % 10));
                if (st & cm) st ^= tm;
            }
            const int s7 = sigt[ri][0], s8 = sigt[ri][1], s9 = sigt[ri][2];
#pragma unroll
            for (int q = 0; q < 8; q++) {
                int idx = st ^ ((q & 1) ? s7 : 0) ^ ((q & 2) ? s8 : 0) ^ ((q & 4) ? s9 : 0);
                s[q] = base[idx];
            }
            pb ^= 1;
        }

        // ---- Rot^dagger on all wires (commuting; grouped by comm pattern) ----
        // wires 0..2 (bits 9..7 = q bits 2..0): thread-local
#pragma unroll
        for (int w = 0; w <= 2; w++) {
            const float2 g00 = gl[w * 4], g01 = gl[w * 4 + 1];
            const float2 g10 = gl[w * 4 + 2], g11 = gl[w * 4 + 3];
            const int qd = 4 >> w;
#pragma unroll
            for (int q = 0; q < 8; q++) {
                if (!(q & qd)) {
                    float2 a0 = s[q], a1 = s[q + qd];
                    s[q]      = cadd(cmul(g00, a0), cmul(g01, a1));
                    s[q + qd] = cadd(cmul(g10, a0), cmul(g11, a1));
                }
            }
        }
        // wires 3..4 (bits 6..5 of tc): smem exchange, warp-uniform branch
#pragma unroll
        for (int w = 3; w <= 4; w++) {
            const float2 g00 = gl[w * 4], g01 = gl[w * 4 + 1];
            const float2 g10 = gl[w * 4 + 2], g11 = gl[w * 4 + 3];
            const int b = 9 - w;
            const int d = 1 << b;
            float2* base = dbuf + (pb * CPB + cid) * 1024;
#pragma unroll
            for (int q = 0; q < 8; q++) base[tc + (q << 7)] = s[q];
            __syncthreads();
            const int pt = tc ^ d;
            if ((tc >> b) & 1) {
#pragma unroll
                for (int q = 0; q < 8; q++) {
                    float2 p = base[pt + (q << 7)];
                    s[q] = cadd(cmul(g10, p), cmul(g11, s[q]));
                }
            } else {
#pragma unroll
                for (int q = 0; q < 8; q++) {
                    float2 p = base[pt + (q << 7)];
                    s[q] = cadd(cmul(g00, s[q]), cmul(g01, p));
                }
            }
            pb ^= 1;
        }
        // wires 5..9 (lane bits): shfl with hoisted gate select (no dual-arm)
#pragma unroll
        for (int w = 5; w <= 9; w++) {
            const float2 g00 = gl[w * 4], g01 = gl[w * 4 + 1];
            const float2 g10 = gl[w * 4 + 2], g11 = gl[w * 4 + 3];
            const int b = 9 - w;
            const int d = 1 << b;
            const bool hi = (lane >> b) & 1;
            const float2 gS = hi ? g11 : g00;   // coeff of own amp
            const float2 gP = hi ? g10 : g01;   // coeff of partner amp
#pragma unroll
            for (int q = 0; q < 8; q++) {
                float2 p;
                p.x = __shfl_xor_sync(0xffffffffu, s[q].x, d);
                p.y = __shfl_xor_sync(0xffffffffu, s[q].y, d);
                s[q] = cadd(cmul(gS, s[q]), cmul(gP, p));
            }
        }
    }
    // U[j,k] = conj(v[k]) -> B'[2j][k] = v.x, B'[2j+1][k] = -v.y
    __half* rowR = g_Bb + (size_t)(2 * col) * KBIG;
    __half* rowI = rowR + KBIG;
#pragma unroll
    for (int q = 0; q < 8; q++) {
        const int k = tc + (q << 7);
        rowR[k] = __float2half_rn(s[q].x);
        rowI[k] = __float2half_rn(-s[q].y);
    }
}

// ---------------- kernel: mma.sync fp16 GEMM + epilogue ----------------
#define STAGE_BYTES 32768
#define GEMM_SMEM   (3 * STAGE_BYTES)   // 98304

__device__ __forceinline__ void load_tile(uint32_t sbase, int stage, int kt,
                                          const __half* gA,
                                          const __half* gB, int tid) {
    const uint32_t aS = sbase + stage * STAGE_BYTES;
    const uint32_t bS = aS + 16384;
    const int r0 = tid >> 3;
    const int c  = tid & 7;
    const uint32_t cx = (uint32_t)(c * 16);
#pragma unroll
    for (int p = 0; p < 4; p++) {
        const int row = p * 32 + r0;
        const uint32_t off = (uint32_t)(row * 128) + (cx ^ ((row & 7) * 16));
        cp_async16(aS + off, gA + (size_t)row * KBIG + (size_t)kt * BKT + c * 8);
    }
#pragma unroll
    for (int p = 0; p < 4; p++) {
        const int row = p * 32 + r0;
        const uint32_t off = (uint32_t)(row * 128) + (cx ^ ((row & 7) * 16));
        cp_async16(bS + off, gB + (size_t)row * KBIG + (size_t)kt * BKT + c * 8);
    }
}

__global__ __launch_bounds__(256, 2) void k_gemm(float* __restrict__ out) {
    extern __shared__ char smem[];
    const uint32_t sbase = smem_u32(smem);
    const int tid = threadIdx.x;
    const int wid = tid >> 5, lane = tid & 31;
    const int wm = wid & 1, wn = wid >> 1;      // 2 x 4 warp grid
    const int m0 = blockIdx.x * 128;
    const int n0 = blockIdx.y * 128;

    const __half* gA = g_As + (size_t)m0 * KBIG;
    const __half* gB = g_Bb + (size_t)n0 * KBIG;

    float acc[4][4][4];
#pragma unroll
    for (int i = 0; i < 4; i++)
#pragma unroll
        for (int j = 0; j < 4; j++)
#pragma unroll
            for (int q = 0; q < 4; q++) acc[i][j][q] = 0.f;

    load_tile(sbase, 0, 0, gA, gB, tid); CP_COMMIT();
    load_tile(sbase, 1, 1, gA, gB, tid); CP_COMMIT();

    const int a_row = wm * 64 + (lane & 7) + ((lane >> 3) & 1) * 8;
    const uint32_t a_kx = ((lane >> 4) & 1) * 16;
    const int b_row = wn * 32 + (lane & 7) + ((lane >> 4) & 1) * 8;
    const uint32_t b_kx = ((lane >> 3) & 1) * 16;

    int stage = 0;
    for (int kt = 0; kt < NKT; kt++) {
        if (kt + 2 < NKT) load_tile(sbase, (stage + 2) % 3, kt + 2, gA, gB, tid);
        CP_COMMIT();
        CP_WAIT2();
        __syncthreads();

        const uint32_t aS = sbase + stage * STAGE_BYTES;
        const uint32_t bS = aS + 16384;
#pragma unroll
        for (int ks = 0; ks < 4; ks++) {
            uint32_t afr[4][4], bfr[2][4];
#pragma unroll
            for (int mf = 0; mf < 4; mf++) {
                const int row = a_row + mf * 16;
                const uint32_t kb = (uint32_t)(ks * 32) + a_kx;
                ldsm_x4(afr[mf], aS + (uint32_t)(row * 128) + (kb ^ ((row & 7) * 16)));
            }
#pragma unroll
            for (int nf2 = 0; nf2 < 2; nf2++) {
                const int row = b_row + nf2 * 16;
                const uint32_t kb = (uint32_t)(ks * 32) + b_kx;
                ldsm_x4(bfr[nf2], bS + (uint32_t)(row * 128) + (kb ^ ((row & 7) * 16)));
            }
#pragma unroll
            for (int mf = 0; mf < 4; mf++)
#pragma unroll
                for (int nf = 0; nf < 4; nf++)
                    mma16816(acc[mf][nf], afr[mf], &bfr[nf >> 1][(nf & 1) * 2]);
        }
        __syncthreads();
        stage = (stage + 1) % 3;
    }

    const int jbase = (n0 >> 1) + wn * 16;
    const int rbase = m0 + wm * 64 + (lane >> 2);
    const int jq = lane & 3;
#pragma unroll
    for (int mf = 0; mf < 4; mf++) {
#pragma unroll
        for (int nf = 0; nf < 4; nf++) {
            const int j = jbase + nf * 4 + jq;
            if (j < PIX) {
                const float re0 = acc[mf][nf][0], im0 = acc[mf][nf][1];
                const float re1 = acc[mf][nf][2], im1 = acc[mf][nf][3];
                out[(size_t)(rbase + mf * 16) * PIX + j] =
                    fminf((re0 * re0 + im0 * im0) * (float)PIX, 1.0f);
                out[(size_t)(rbase + mf * 16 + 8) * PIX + j] =
                    fminf((re1 * re1 + im1 * im1) * (float)PIX, 1.0f);
            }
        }
    }
}

// ---------------- launch ----------------
extern "C" void kernel_launch(void* const* d_in, const int* in_sizes, int n_in,
                              void* d_out, int out_size) {
    const float* x  = (const float*)d_in[0];
    const float* W  = (const float*)d_in[1];
    const float* b  = (const float*)d_in[2];
    const float* qw = (const float*)d_in[3];
    float* out = (float*)d_out;

    cudaFuncSetAttribute(k_gemm, cudaFuncAttributeMaxDynamicSharedMemorySize, GEMM_SMEM);
    cudaFuncSetAttribute(k_buildU, cudaFuncAttributeMaxDynamicSharedMemorySize, BUILD_SMEM);

    k_gates<<<1, 256>>>(qw);                        // launch 1
    k_angA<<<BATCH / 8, 256>>>(x, W, b);            // launch 2
    k_buildU<<<NJ / CPB, 512, BUILD_SMEM>>>();      // launch 3 (208 blocks)
    dim3 gg(BATCH / 128, NBIG / 128);               // 64 x 13
    k_gemm<<<gg, 256, GEMM_SMEM>>>(out);            // launch 4 (profiled)
}

// round 15
// speedup vs baseline: 1.4988x; 1.0283x over previous
#include <cuda_runtime.h>
#include <cuda_fp16.h>
#include <math.h>
#include <stdint.h>

#define BATCH 8192
#define PIX 784
#define WIRES 10
#define DIM 1024
#define QDEPTH 20
#define NGATES (QDEPTH * WIRES)   // 200

#define KBIG 1024                 // pure fp16: A=fp16(S), B=fp16(U)
#define NBIG 1664                 // 832 j-slots x (re,im) interleaved
#define NJ   (NBIG / 2)           // 832 rows of U actually needed
#define BKT  64                   // K per smem tile
#define NKT  (KBIG / BKT)         // 16

// ---------------- scratch ----------------
__device__ float2 g_gates[NGATES * 4];          // ADJOINT Rot gates
__device__ __half g_As[(size_t)BATCH * KBIG];   // A' [m][k]
__device__ __half g_Bb[(size_t)NBIG * KBIG];    // GEMM B: [n][k]

// ---------------- helpers ----------------
__device__ __forceinline__ uint32_t smem_u32(const void* p) {
    uint32_t a;
    asm("{ .reg .u64 t; cvta.to.shared.u64 t, %1; cvt.u32.u64 %0, t; }" : "=r"(a) : "l"(p));
    return a;
}
__device__ __forceinline__ void cp_async16(uint32_t dst, const void* src) {
    asm volatile("cp.async.cg.shared.global [%0], [%1], 16;" :: "r"(dst), "l"(src));
}
#define CP_COMMIT() asm volatile("cp.async.commit_group;" ::: "memory")
#define CP_WAIT1()  asm volatile("cp.async.wait_group 1;" ::: "memory")

__device__ __forceinline__ void ldsm_x4(uint32_t* r, uint32_t addr) {
    asm volatile("ldmatrix.sync.aligned.m8n8.x4.shared.b16 {%0,%1,%2,%3}, [%4];"
                 : "=r"(r[0]), "=r"(r[1]), "=r"(r[2]), "=r"(r[3]) : "r"(addr));
}
__device__ __forceinline__ void mma16816(float* d, const uint32_t* a, const uint32_t* b) {
    asm volatile(
        "mma.sync.aligned.m16n8k16.row.col.f32.f16.f16.f32 "
        "{%0,%1,%2,%3}, {%4,%5,%6,%7}, {%8,%9}, {%0,%1,%2,%3};"
        : "+f"(d[0]), "+f"(d[1]), "+f"(d[2]), "+f"(d[3])
        : "r"(a[0]), "r"(a[1]), "r"(a[2]), "r"(a[3]), "r"(b[0]), "r"(b[1]));
}
__device__ __forceinline__ float2 cmul(float2 g, float2 v) {
    return make_float2(g.x * v.x - g.y * v.y, g.x * v.y + g.y * v.x);
}
__device__ __forceinline__ float2 cadd(float2 a, float2 b) {
    return make_float2(a.x + b.x, a.y + b.y);
}

// ---- packed f32x2 helpers (sm_100 base ISA) ----
__device__ __forceinline__ uint64_t bc2(float v) {
    uint64_t r; asm("mov.b64 %0, {%1, %1};" : "=l"(r) : "f"(v)); return r;
}
__device__ __forceinline__ uint64_t pk2(float lo, float hi) {
    uint64_t r; asm("mov.b64 %0, {%1, %2};" : "=l"(r) : "f"(lo), "f"(hi)); return r;
}
__device__ __forceinline__ void upk2(float& lo, float& hi, uint64_t v) {
    asm("mov.b64 {%0, %1}, %2;" : "=f"(lo), "=f"(hi) : "l"(v));
}
__device__ __forceinline__ uint64_t f2fma(uint64_t a, uint64_t b, uint64_t c) {
    uint64_t d; asm("fma.rn.f32x2 %0, %1, %2, %3;" : "=l"(d) : "l"(a), "l"(b), "l"(c));
    return d;
}
__device__ __forceinline__ uint64_t f2mul(uint64_t a, uint64_t b) {
    uint64_t d; asm("mul.rn.f32x2 %0, %1, %2;" : "=l"(d) : "l"(a), "l"(b));
    return d;
}
struct __align__(16) pc2 { uint64_t x, y; };   // packed (re0,re1), (im0,im1)
// r = g * a (complex, both packed lanes share scalar gate g)
__device__ __forceinline__ pc2 pcmul(float2 g, pc2 a) {
    pc2 r;
    r.x = f2fma(bc2(-g.y), a.y, f2mul(bc2(g.x), a.x));
    r.y = f2fma(bc2(g.y),  a.x, f2mul(bc2(g.x), a.y));
    return r;
}
// acc += g * a
__device__ __forceinline__ pc2 pcfma(float2 g, pc2 a, pc2 acc) {
    acc.x = f2fma(bc2(g.x), a.x, f2fma(bc2(-g.y), a.y, acc.x));
    acc.y = f2fma(bc2(g.x), a.y, f2fma(bc2(g.y),  a.x, acc.y));
    return acc;
}

// ---------------- kernel: ADJOINT Rot gates ----------------
__global__ void k_gates(const float* __restrict__ qw) {
    int g = blockIdx.x * blockDim.x + threadIdx.x;
    if (g >= NGATES) return;
    float phi = qw[g * 3 + 0], th = qw[g * 3 + 1], om = qw[g * 3 + 2];
    float c = cosf(0.5f * th), s = sinf(0.5f * th);
    float A = 0.5f * (phi + om), B = 0.5f * (phi - om);
    float cA = cosf(A), sA = sinf(A), cB = cosf(B), sB = sinf(B);
    g_gates[g * 4 + 0] = make_float2(cA * c,  sA * c);    // conj(m00)
    g_gates[g * 4 + 1] = make_float2(cB * s,  sB * s);    // conj(m10)
    g_gates[g * 4 + 2] = make_float2(-cB * s, sB * s);    // conj(m01)
    g_gates[g * 4 + 3] = make_float2(cA * c, -sA * c);    // conj(m11)
}

// ---------------- kernel: fused angles + fp16 product state ----------------
__global__ __launch_bounds__(256) void k_angA(const float* __restrict__ x,
                                              const float* __restrict__ W,
                                              const float* __restrict__ bias) {
    const int warp = blockIdx.x * 8 + (threadIdx.x >> 5);
    const int lane = threadIdx.x & 31;
    const float4* xr4 = (const float4*)(x + (size_t)warp * PIX);
    float acc[WIRES];
#pragma unroll
    for (int w = 0; w < WIRES; w++) acc[w] = 0.f;
    for (int p4 = lane; p4 < PIX / 4; p4 += 32) {
        const float4 xv = xr4[p4];
#pragma unroll
        for (int w = 0; w < WIRES; w++) {
            const float4 wv = __ldg((const float4*)(W + w * PIX) + p4);
            acc[w] = fmaf(xv.x, wv.x, acc[w]);
            acc[w] = fmaf(xv.y, wv.y, acc[w]);
            acc[w] = fmaf(xv.z, wv.z, acc[w]);
            acc[w] = fmaf(xv.w, wv.w, acc[w]);
        }
    }
#pragma unroll
    for (int w = 0; w < WIRES; w++) {
#pragma unroll
        for (int o = 16; o; o >>= 1)
            acc[w] += __shfl_xor_sync(0xffffffffu, acc[w], o);
    }
    float cl = 1.f, cr = 1.f;
#pragma unroll
    for (int w = 0; w < 5; w++) {
        float h = 0.5f * (acc[w] + __ldg(&bias[w]));
        float s, c; sincosf(h, &s, &c);
        cl *= ((lane >> (4 - w)) & 1) ? s : c;
    }
#pragma unroll
    for (int w = 5; w < 10; w++) {
        float h = 0.5f * (acc[w] + __ldg(&bias[w]));
        float s, c; sincosf(h, &s, &c);
        cr *= ((lane >> (9 - w)) & 1) ? s : c;
    }
    char* rowb = (char*)(g_As + (size_t)warp * KBIG) + lane * 64;
#pragma unroll
    for (int q = 0; q < 32; q += 8) {
        uint32_t u[4];
#pragma unroll
        for (int j = 0; j < 4; j++) {
            float r0 = __shfl_sync(0xffffffffu, cr, q + 2 * j);
            float r1 = __shfl_sync(0xffffffffu, cr, q + 2 * j + 1);
            __half2 h2 = __floats2half2_rn(cl * r0, cl * r1);
            u[j] = *(uint32_t*)&h2;
        }
        *(uint4*)(rowb + q * 2) = make_uint4(u[0], u[1], u[2], u[3]);
    }
}

// ---------------- kernel: INVERSE circuit, packed f32x2 state ----------------
// State: 4 packed pairs; pair i holds amps {tc + 2i*128, tc + (2i+1)*128}.
// Amp bit map: bit9=pair-idx bit1(w0), bit8=pair-idx bit0(w1), bit7=packed lane(w2),
// bits6,5 = tc bits (w3,w4 smem), bits4..0 = lane bits (w5..9 shfl).
#define CPB 4
#define TPC 128
#define BUILD_SMEM (2 * CPB * 512 * 16)   // 65536 bytes

__global__ __launch_bounds__(512, 2) void k_buildU() {
    extern __shared__ char draw[];
    __shared__ float2 gs[NGATES * 4];
    __shared__ int sigt[9][3];
    const int tid = threadIdx.x;
    const int tc = tid & (TPC - 1);
    const int cid = tid >> 7;
    const int lane = tid & 31;
    const int col = blockIdx.x * CPB + cid;   // j in [0, 832)

    for (int i = tid; i < NGATES * 4; i += 512) gs[i] = g_gates[i];
    if (tid < 27) {
        int r = tid / 3 + 1, bsel = tid % 3;
        int p = 128 << bsel;
#pragma unroll
        for (int w = 0; w <= 9; w++) {          // ASCENDING = inverse ring
            int cm = 1 << (9 - w);
            int tm = 1 << (9 - ((w + r) % 10));
            if (p & cm) p ^= tm;
        }
        sigt[tid / 3][bsel] = p;
    }
    pc2 S[4];
#pragma unroll
    for (int i = 0; i < 4; i++) {
        S[i].x = pk2((tc + (2 * i) * 128) == col ? 1.f : 0.f,
                     (tc + (2 * i + 1) * 128) == col ? 1.f : 0.f);
        S[i].y = bc2(0.f);
    }
    __syncthreads();

    int pb = 0;
    for (int ll = 0; ll < QDEPTH; ll++) {
        const int l = QDEPTH - 1 - ll;
        const float2* gl = &gs[l * WIRES * 4];

        // ---- inverse CNOT ring: scalar float2 scatter/gather ----
        {
            const int ri = l % 9;
            const int r = ri + 1;
            float2* base = (float2*)draw + (pb * CPB + cid) * 1024;
#pragma unroll
            for (int i = 0; i < 4; i++) {
                float x0, x1, y0, y1;
                upk2(x0, x1, S[i].x); upk2(y0, y1, S[i].y);
                base[tc + (2 * i) * 128]     = make_float2(x0, y0);
                base[tc + (2 * i + 1) * 128] = make_float2(x1, y1);
            }
            __syncthreads();
            int st = tc;
#pragma unroll
            for (int w = 0; w <= 9; w++) {
                int cm = 1 << (9 - w);
                int tm = 1 << (9 - ((w + r) % 10));
                if (st & cm) st ^= tm;
            }
            const int s7 = sigt[ri][0], s8 = sigt[ri][1], s9 = sigt[ri][2];
            float2 gval[8];
#pragma unroll
            for (int q = 0; q < 8; q++) {
                int idx = st ^ ((q & 1) ? s7 : 0) ^ ((q & 2) ? s8 : 0) ^ ((q & 4) ? s9 : 0);
                gval[q] = base[idx];
            }
#pragma unroll
            for (int i = 0; i < 4; i++) {
                S[i].x = pk2(gval[2 * i].x, gval[2 * i + 1].x);
                S[i].y = pk2(gval[2 * i].y, gval[2 * i + 1].y);
            }
            pb ^= 1;
        }

        // ---- wire 0 (pair-idx bit 1): pairs (0,2),(1,3) ----
        {
            const float2 g00 = gl[0], g01 = gl[1], g10 = gl[2], g11 = gl[3];
#pragma unroll
            for (int i = 0; i < 2; i++) {
                pc2 a0 = S[i], a1 = S[i + 2];
                S[i]     = pcfma(g01, a1, pcmul(g00, a0));
                S[i + 2] = pcfma(g11, a1, pcmul(g10, a0));
            }
        }
        // ---- wire 1 (pair-idx bit 0): pairs (0,1),(2,3) ----
        {
            const float2 g00 = gl[4], g01 = gl[5], g10 = gl[6], g11 = gl[7];
#pragma unroll
            for (int i = 0; i < 4; i += 2) {
                pc2 a0 = S[i], a1 = S[i + 1];
                S[i]     = pcfma(g01, a1, pcmul(g00, a0));
                S[i + 1] = pcfma(g11, a1, pcmul(g10, a0));
            }
        }
        // ---- wire 2 (packed lane): scalar within each pair ----
        {
            const float2 g00 = gl[8], g01 = gl[9], g10 = gl[10], g11 = gl[11];
#pragma unroll
            for (int i = 0; i < 4; i++) {
                float x0, x1, y0, y1;
                upk2(x0, x1, S[i].x); upk2(y0, y1, S[i].y);
                float2 a0 = make_float2(x0, y0), a1 = make_float2(x1, y1);
                float2 n0 = cadd(cmul(g00, a0), cmul(g01, a1));
                float2 n1 = cadd(cmul(g10, a0), cmul(g11, a1));
                S[i].x = pk2(n0.x, n1.x); S[i].y = pk2(n0.y, n1.y);
            }
        }
        // ---- wires 3,4 (tc bits 6,5): smem exchange, packed, uniform branch ----
#pragma unroll
        for (int w = 3; w <= 4; w++) {
            const float2 g00 = gl[w * 4], g01 = gl[w * 4 + 1];
            const float2 g10 = gl[w * 4 + 2], g11 = gl[w * 4 + 3];
            const int b = 9 - w;
            const int d = 1 << b;
            pc2* pp = (pc2*)draw + (pb * CPB + cid) * 512;
#pragma unroll
            for (int i = 0; i < 4; i++) pp[i * 128 + tc] = S[i];
            __syncthreads();
            const int pt = tc ^ d;
            const bool hi = (tc >> b) & 1;
            const float2 gS = hi ? g11 : g00;
            const float2 gP = hi ? g10 : g01;
#pragma unroll
            for (int i = 0; i < 4; i++) {
                pc2 P = pp[i * 128 + pt];
                S[i] = pcfma(gP, P, pcmul(gS, S[i]));
            }
            pb ^= 1;
        }
        // ---- wires 5..9 (lane bits): shfl, packed, hoisted select ----
#pragma unroll
        for (int w = 5; w <= 9; w++) {
            const float2 g00 = gl[w * 4], g01 = gl[w * 4 + 1];
            const float2 g10 = gl[w * 4 + 2], g11 = gl[w * 4 + 3];
            const int b = 9 - w;
            const int d = 1 << b;
            const bool hi = (lane >> b) & 1;
            const float2 gS = hi ? g11 : g00;
            const float2 gP = hi ? g10 : g01;
#pragma unroll
            for (int i = 0; i < 4; i++) {
                pc2 P;
                P.x = __shfl_xor_sync(0xffffffffu, (unsigned long long)S[i].x, d);
                P.y = __shfl_xor_sync(0xffffffffu, (unsigned long long)S[i].y, d);
                S[i] = pcfma(gP, P, pcmul(gS, S[i]));
            }
        }
    }
    // U[j,k] = conj(v[k]) -> B'[2j][k] = v.x, B'[2j+1][k] = -v.y
    __half* rowR = g_Bb + (size_t)(2 * col) * KBIG;
    __half* rowI = rowR + KBIG;
#pragma unroll
    for (int i = 0; i < 4; i++) {
        float x0, x1, y0, y1;
        upk2(x0, x1, S[i].x); upk2(y0, y1, S[i].y);
        rowR[tc + (2 * i) * 128]     = __float2half_rn(x0);
        rowR[tc + (2 * i + 1) * 128] = __float2half_rn(x1);
        rowI[tc + (2 * i) * 128]     = __float2half_rn(-y0);
        rowI[tc + (2 * i + 1) * 128] = __float2half_rn(-y1);
    }
}

// ---------------- kernel: mma.sync fp16 GEMM + epilogue ----------------
#define STAGE_BYTES 32768
#define GEMM_SMEM   (3 * STAGE_BYTES)   // 98304

__device__ __forceinline__ void load_tile(uint32_t sbase, int stage, int kt,
                                          const __half* gA,
                                          const __half* gB, int tid) {
    const uint32_t aS = sbase + stage * STAGE_BYTES;
    const uint32_t bS = aS + 16384;
    const int r0 = tid >> 3;
    const int c  = tid & 7;
    const uint32_t cx = (uint32_t)(c * 16);
#pragma unroll
    for (int p = 0; p < 4; p++) {
        const int row = p * 32 + r0;
        const uint32_t off = (uint32_t)(row * 128) + (cx ^ ((row & 7) * 16));
        cp_async16(aS + off, gA + (size_t)row * KBIG + (size_t)kt * BKT + c * 8);
    }
#pragma unroll
    for (int p = 0; p < 4; p++) {
        const int row = p * 32 + r0;
        const uint32_t off = (uint32_t)(row * 128) + (cx ^ ((row & 7) * 16));
        cp_async16(bS + off, gB + (size_t)row * KBIG + (size_t)kt * BKT + c * 8);
    }
}

__global__ __launch_bounds__(256, 2) void k_gemm(float* __restrict__ out) {
    extern __shared__ char smem[];
    const uint32_t sbase = smem_u32(smem);
    const int tid = threadIdx.x;
    const int wid = tid >> 5, lane = tid & 31;
    const int wm = wid & 1, wn = wid >> 1;      // 2 x 4 warp grid
    const int m0 = blockIdx.x * 128;
    const int n0 = blockIdx.y * 128;

    const __half* gA = g_As + (size_t)m0 * KBIG;
    const __half* gB = g_Bb + (size_t)n0 * KBIG;

    float acc[4][4][4];
#pragma unroll
    for (int i = 0; i < 4; i++)
#pragma unroll
        for (int j = 0; j < 4; j++)
#pragma unroll
            for (int q = 0; q < 4; q++) acc[i][j][q] = 0.f;

    load_tile(sbase, 0, 0, gA, gB, tid); CP_COMMIT();
    load_tile(sbase, 1, 1, gA, gB, tid); CP_COMMIT();

    const int a_row = wm * 64 + (lane & 7) + ((lane >> 3) & 1) * 8;
    const uint32_t a_kx = ((lane >> 4) & 1) * 16;
    const int b_row = wn * 32 + (lane & 7) + ((lane >> 4) & 1) * 8;
    const uint32_t b_kx = ((lane >> 3) & 1) * 16;

    for (int kt = 0; kt < NKT; kt++) {
        CP_WAIT1();
        __syncthreads();
        if (kt + 2 < NKT) load_tile(sbase, (kt + 2) % 3, kt + 2, gA, gB, tid);
        CP_COMMIT();

        const uint32_t aS = sbase + (kt % 3) * STAGE_BYTES;
        const uint32_t bS = aS + 16384;
#pragma unroll
        for (int ks = 0; ks < 4; ks++) {
            uint32_t afr[4][4], bfr[2][4];
#pragma unroll
            for (int mf = 0; mf < 4; mf++) {
                const int row = a_row + mf * 16;
                const uint32_t kb = (uint32_t)(ks * 32) + a_kx;
                ldsm_x4(afr[mf], aS + (uint32_t)(row * 128) + (kb ^ ((row & 7) * 16)));
            }
#pragma unroll
            for (int nf2 = 0; nf2 < 2; nf2++) {
                const int row = b_row + nf2 * 16;
                const uint32_t kb = (uint32_t)(ks * 32) + b_kx;
                ldsm_x4(bfr[nf2], bS + (uint32_t)(row * 128) + (kb ^ ((row & 7) * 16)));
            }
#pragma unroll
            for (int mf = 0; mf < 4; mf++)
#pragma unroll
                for (int nf = 0; nf < 4; nf++)
                    mma16816(acc[mf][nf], afr[mf], &bfr[nf >> 1][(nf & 1) * 2]);
        }
    }

    const int jbase = (n0 >> 1) + wn * 16;
    const int rbase = m0 + wm * 64 + (lane >> 2);
    const int jq = lane & 3;
#pragma unroll
    for (int mf = 0; mf < 4; mf++) {
#pragma unroll
        for (int nf = 0; nf < 4; nf++) {
            const int j = jbase + nf * 4 + jq;
            if (j < PIX) {
                const float re0 = acc[mf][nf][0], im0 = acc[mf][nf][1];
                const float re1 = acc[mf][nf][2], im1 = acc[mf][nf][3];
                out[(size_t)(rbase + mf * 16) * PIX + j] =
                    fminf((re0 * re0 + im0 * im0) * (float)PIX, 1.0f);
                out[(size_t)(rbase + mf * 16 + 8) * PIX + j] =
                    fminf((re1 * re1 + im1 * im1) * (float)PIX, 1.0f);
            }
        }
    }
}

// ---------------- launch ----------------
extern "C" void kernel_launch(void* const* d_in, const int* in_sizes, int n_in,
                              void* d_out, int out_size) {
    const float* x  = (const float*)d_in[0];
    const float* W  = (const float*)d_in[1];
    const float* b  = (const float*)d_in[2];
    const float* qw = (const float*)d_in[3];
    float* out = (float*)d_out;

    cudaFuncSetAttribute(k_gemm, cudaFuncAttributeMaxDynamicSharedMemorySize, GEMM_SMEM);
    cudaFuncSetAttribute(k_buildU, cudaFuncAttributeMaxDynamicSharedMemorySize, BUILD_SMEM);

    k_gates<<<1, 256>>>(qw);                        // launch 1
    k_angA<<<BATCH / 8, 256>>>(x, W, b);            // launch 2
    k_buildU<<<NJ / CPB, 512, BUILD_SMEM>>>();      // launch 3 (208 blocks)
    dim3 gg(BATCH / 128, NBIG / 128);               // 64 x 13
    k_gemm<<<gg, 256, GEMM_SMEM>>>(out);            // launch 4 (profiled)
}

// round 16
// speedup vs baseline: 1.7639x; 1.1769x over previous
#include <cuda_runtime.h>
#include <cuda_fp16.h>
#include <math.h>
#include <stdint.h>

#define BATCH 8192
#define PIX 784
#define WIRES 10
#define DIM 1024
#define QDEPTH 20
#define NGATES (QDEPTH * WIRES)   // 200

#define KBIG 1024                 // pure fp16: A=fp16(S), B=fp16(U)
#define NBIG 1664                 // 832 j-slots x (re,im) interleaved
#define NJ   (NBIG / 2)           // 832 rows of U actually needed
#define BKT  64                   // K per smem tile
#define NKT  (KBIG / BKT)         // 16

// ---------------- scratch ----------------
__device__ float2 g_gates[NGATES * 4];          // ADJOINT Rot gates
__device__ __half g_As[(size_t)BATCH * KBIG];   // A' [m][k]
__device__ __half g_Bb[(size_t)NBIG * KBIG];    // GEMM B: [n][k]

// ---------------- helpers ----------------
__device__ __forceinline__ uint32_t smem_u32(const void* p) {
    uint32_t a;
    asm("{ .reg .u64 t; cvta.to.shared.u64 t, %1; cvt.u32.u64 %0, t; }" : "=r"(a) : "l"(p));
    return a;
}
__device__ __forceinline__ void cp_async16(uint32_t dst, const void* src) {
    asm volatile("cp.async.cg.shared.global [%0], [%1], 16;" :: "r"(dst), "l"(src));
}
#define CP_COMMIT() asm volatile("cp.async.commit_group;" ::: "memory")
#define CP_WAIT1()  asm volatile("cp.async.wait_group 1;" ::: "memory")

__device__ __forceinline__ void ldsm_x4(uint32_t* r, uint32_t addr) {
    asm volatile("ldmatrix.sync.aligned.m8n8.x4.shared.b16 {%0,%1,%2,%3}, [%4];"
                 : "=r"(r[0]), "=r"(r[1]), "=r"(r[2]), "=r"(r[3]) : "r"(addr));
}
__device__ __forceinline__ void mma16816(float* d, const uint32_t* a, const uint32_t* b) {
    asm volatile(
        "mma.sync.aligned.m16n8k16.row.col.f32.f16.f16.f32 "
        "{%0,%1,%2,%3}, {%4,%5,%6,%7}, {%8,%9}, {%0,%1,%2,%3};"
        : "+f"(d[0]), "+f"(d[1]), "+f"(d[2]), "+f"(d[3])
        : "r"(a[0]), "r"(a[1]), "r"(a[2]), "r"(a[3]), "r"(b[0]), "r"(b[1]));
}
__device__ __forceinline__ float2 cmul(float2 g, float2 v) {
    return make_float2(g.x * v.x - g.y * v.y, g.x * v.y + g.y * v.x);
}
__device__ __forceinline__ float2 cadd(float2 a, float2 b) {
    return make_float2(a.x + b.x, a.y + b.y);
}

// ---- packed f32x2 helpers (sm_100 base ISA) ----
__device__ __forceinline__ uint64_t bc2(float v) {
    uint64_t r; asm("mov.b64 %0, {%1, %1};" : "=l"(r) : "f"(v)); return r;
}
__device__ __forceinline__ uint64_t pk2(float lo, float hi) {
    uint64_t r; asm("mov.b64 %0, {%1, %2};" : "=l"(r) : "f"(lo), "f"(hi)); return r;
}
__device__ __forceinline__ void upk2(float& lo, float& hi, uint64_t v) {
    asm("mov.b64 {%0, %1}, %2;" : "=f"(lo), "=f"(hi) : "l"(v));
}
__device__ __forceinline__ uint64_t f2fma(uint64_t a, uint64_t b, uint64_t c) {
    uint64_t d; asm("fma.rn.f32x2 %0, %1, %2, %3;" : "=l"(d) : "l"(a), "l"(b), "l"(c));
    return d;
}
__device__ __forceinline__ uint64_t f2mul(uint64_t a, uint64_t b) {
    uint64_t d; asm("mul.rn.f32x2 %0, %1, %2;" : "=l"(d) : "l"(a), "l"(b));
    return d;
}
struct __align__(16) pc2 { uint64_t x, y; };   // packed (re0,re1), (im0,im1)
__device__ __forceinline__ pc2 pcmul(float2 g, pc2 a) {
    pc2 r;
    r.x = f2fma(bc2(-g.y), a.y, f2mul(bc2(g.x), a.x));
    r.y = f2fma(bc2(g.y),  a.x, f2mul(bc2(g.x), a.y));
    return r;
}
__device__ __forceinline__ pc2 pcfma(float2 g, pc2 a, pc2 acc) {
    acc.x = f2fma(bc2(g.x), a.x, f2fma(bc2(-g.y), a.y, acc.x));
    acc.y = f2fma(bc2(g.x), a.y, f2fma(bc2(g.y),  a.x, acc.y));
    return acc;
}

// ---------------- kernel: ADJOINT Rot gates ----------------
__global__ void k_gates(const float* __restrict__ qw) {
    int g = blockIdx.x * blockDim.x + threadIdx.x;
    if (g >= NGATES) return;
    float phi = qw[g * 3 + 0], th = qw[g * 3 + 1], om = qw[g * 3 + 2];
    float c = cosf(0.5f * th), s = sinf(0.5f * th);
    float A = 0.5f * (phi + om), B = 0.5f * (phi - om);
    float cA = cosf(A), sA = sinf(A), cB = cosf(B), sB = sinf(B);
    g_gates[g * 4 + 0] = make_float2(cA * c,  sA * c);    // conj(m00)
    g_gates[g * 4 + 1] = make_float2(cB * s,  sB * s);    // conj(m10)
    g_gates[g * 4 + 2] = make_float2(-cB * s, sB * s);    // conj(m01)
    g_gates[g * 4 + 3] = make_float2(cA * c, -sA * c);    // conj(m11)
}

// ---------------- kernel: fused angles + fp16 product state ----------------
__global__ __launch_bounds__(256) void k_angA(const float* __restrict__ x,
                                              const float* __restrict__ W,
                                              const float* __restrict__ bias) {
    const int warp = blockIdx.x * 8 + (threadIdx.x >> 5);
    const int lane = threadIdx.x & 31;
    const float4* xr4 = (const float4*)(x + (size_t)warp * PIX);
    float acc[WIRES];
#pragma unroll
    for (int w = 0; w < WIRES; w++) acc[w] = 0.f;
    for (int p4 = lane; p4 < PIX / 4; p4 += 32) {
        const float4 xv = xr4[p4];
#pragma unroll
        for (int w = 0; w < WIRES; w++) {
            const float4 wv = __ldg((const float4*)(W + w * PIX) + p4);
            acc[w] = fmaf(xv.x, wv.x, acc[w]);
            acc[w] = fmaf(xv.y, wv.y, acc[w]);
            acc[w] = fmaf(xv.z, wv.z, acc[w]);
            acc[w] = fmaf(xv.w, wv.w, acc[w]);
        }
    }
#pragma unroll
    for (int w = 0; w < WIRES; w++) {
#pragma unroll
        for (int o = 16; o; o >>= 1)
            acc[w] += __shfl_xor_sync(0xffffffffu, acc[w], o);
    }
    float cl = 1.f, cr = 1.f;
#pragma unroll
    for (int w = 0; w < 5; w++) {
        float h = 0.5f * (acc[w] + __ldg(&bias[w]));
        float s, c; sincosf(h, &s, &c);
        cl *= ((lane >> (4 - w)) & 1) ? s : c;
    }
#pragma unroll
    for (int w = 5; w < 10; w++) {
        float h = 0.5f * (acc[w] + __ldg(&bias[w]));
        float s, c; sincosf(h, &s, &c);
        cr *= ((lane >> (9 - w)) & 1) ? s : c;
    }
    char* rowb = (char*)(g_As + (size_t)warp * KBIG) + lane * 64;
#pragma unroll
    for (int q = 0; q < 32; q += 8) {
        uint32_t u[4];
#pragma unroll
        for (int j = 0; j < 4; j++) {
            float r0 = __shfl_sync(0xffffffffu, cr, q + 2 * j);
            float r1 = __shfl_sync(0xffffffffu, cr, q + 2 * j + 1);
            __half2 h2 = __floats2half2_rn(cl * r0, cl * r1);
            u[j] = *(uint32_t*)&h2;
        }
        *(uint4*)(rowb + q * 2) = make_uint4(u[0], u[1], u[2], u[3]);
    }
}

// ---------------- kernel: INVERSE circuit, packed f32x2, 1 col / 128-thr blk -
// Thread owns amps {tid + 128q}, q=0..7, as 4 packed pairs (pair dim = bit 7).
// Amp bits: 9,8 = pair idx (w0,w1), 7 = packed lane (w2), 6,5 = tid bits (w3,w4
// smem), 4..0 = lane bits (w5..w9 shfl). Grid = 832 blocks, 8 blocks/SM.
#define BUILD_SMEM (2 * 512 * 16)   // 16384 bytes (double-buffered 1024 float2)

__global__ __launch_bounds__(128, 8) void k_buildU() {
    extern __shared__ char draw[];
    __shared__ float2 gs[NGATES * 4];
    __shared__ int sigt[9][3];
    const int tc = threadIdx.x;          // 0..127
    const int lane = tc & 31;
    const int col = blockIdx.x;          // j in [0, 832)

    for (int i = tc; i < NGATES * 4; i += 128) gs[i] = g_gates[i];
    if (tc < 27) {
        int r = tc / 3 + 1, bsel = tc % 3;
        int p = 128 << bsel;
#pragma unroll
        for (int w = 0; w <= 9; w++) {          // ASCENDING = inverse ring
            int cm = 1 << (9 - w);
            int tm = 1 << (9 - ((w + r) % 10));
            if (p & cm) p ^= tm;
        }
        sigt[tc / 3][bsel] = p;
    }
    pc2 S[4];
#pragma unroll
    for (int i = 0; i < 4; i++) {
        S[i].x = pk2((tc + (2 * i) * 128) == col ? 1.f : 0.f,
                     (tc + (2 * i + 1) * 128) == col ? 1.f : 0.f);
        S[i].y = bc2(0.f);
    }
    __syncthreads();

    int pb = 0;
    for (int ll = 0; ll < QDEPTH; ll++) {
        const int l = QDEPTH - 1 - ll;
        const float2* gl = &gs[l * WIRES * 4];

        // ---- inverse CNOT ring: scalar float2 scatter/gather ----
        {
            const int ri = l % 9;
            const int r = ri + 1;
            float2* base = (float2*)draw + pb * 1024;
#pragma unroll
            for (int i = 0; i < 4; i++) {
                float x0, x1, y0, y1;
                upk2(x0, x1, S[i].x); upk2(y0, y1, S[i].y);
                base[tc + (2 * i) * 128]     = make_float2(x0, y0);
                base[tc + (2 * i + 1) * 128] = make_float2(x1, y1);
            }
            __syncthreads();
            int st = tc;
#pragma unroll
            for (int w = 0; w <= 9; w++) {
                int cm = 1 << (9 - w);
                int tm = 1 << (9 - ((w + r) % 10));
                if (st & cm) st ^= tm;
            }
            const int s7 = sigt[ri][0], s8 = sigt[ri][1], s9 = sigt[ri][2];
            float2 gval[8];
#pragma unroll
            for (int q = 0; q < 8; q++) {
                int idx = st ^ ((q & 1) ? s7 : 0) ^ ((q & 2) ? s8 : 0) ^ ((q & 4) ? s9 : 0);
                gval[q] = base[idx];
            }
#pragma unroll
            for (int i = 0; i < 4; i++) {
                S[i].x = pk2(gval[2 * i].x, gval[2 * i + 1].x);
                S[i].y = pk2(gval[2 * i].y, gval[2 * i + 1].y);
            }
            pb ^= 1;
        }

        // ---- wire 0 (pair-idx bit 1): pairs (0,2),(1,3) ----
        {
            const float2 g00 = gl[0], g01 = gl[1], g10 = gl[2], g11 = gl[3];
#pragma unroll
            for (int i = 0; i < 2; i++) {
                pc2 a0 = S[i], a1 = S[i + 2];
                S[i]     = pcfma(g01, a1, pcmul(g00, a0));
                S[i + 2] = pcfma(g11, a1, pcmul(g10, a0));
            }
        }
        // ---- wire 1 (pair-idx bit 0): pairs (0,1),(2,3) ----
        {
            const float2 g00 = gl[4], g01 = gl[5], g10 = gl[6], g11 = gl[7];
#pragma unroll
            for (int i = 0; i < 4; i += 2) {
                pc2 a0 = S[i], a1 = S[i + 1];
                S[i]     = pcfma(g01, a1, pcmul(g00, a0));
                S[i + 1] = pcfma(g11, a1, pcmul(g10, a0));
            }
        }
        // ---- wire 2 (packed lane): scalar within each pair ----
        {
            const float2 g00 = gl[8], g01 = gl[9], g10 = gl[10], g11 = gl[11];
#pragma unroll
            for (int i = 0; i < 4; i++) {
                float x0, x1, y0, y1;
                upk2(x0, x1, S[i].x); upk2(y0, y1, S[i].y);
                float2 a0 = make_float2(x0, y0), a1 = make_float2(x1, y1);
                float2 n0 = cadd(cmul(g00, a0), cmul(g01, a1));
                float2 n1 = cadd(cmul(g10, a0), cmul(g11, a1));
                S[i].x = pk2(n0.x, n1.x); S[i].y = pk2(n0.y, n1.y);
            }
        }
        // ---- wires 3,4 (tid bits 6,5): smem exchange, packed, uniform branch --
#pragma unroll
        for (int w = 3; w <= 4; w++) {
            const float2 g00 = gl[w * 4], g01 = gl[w * 4 + 1];
            const float2 g10 = gl[w * 4 + 2], g11 = gl[w * 4 + 3];
            const int b = 9 - w;
            const int d = 1 << b;
            pc2* pp = (pc2*)draw + pb * 512;
#pragma unroll
            for (int i = 0; i < 4; i++) pp[i * 128 + tc] = S[i];
            __syncthreads();
            const int pt = tc ^ d;
            const bool hi = (tc >> b) & 1;
            const float2 gS = hi ? g11 : g00;
            const float2 gP = hi ? g10 : g01;
#pragma unroll
            for (int i = 0; i < 4; i++) {
                pc2 P = pp[i * 128 + pt];
                S[i] = pcfma(gP, P, pcmul(gS, S[i]));
            }
            pb ^= 1;
        }
        // ---- wires 5..9 (lane bits): shfl, packed, hoisted select ----
#pragma unroll
        for (int w = 5; w <= 9; w++) {
            const float2 g00 = gl[w * 4], g01 = gl[w * 4 + 1];
            const float2 g10 = gl[w * 4 + 2], g11 = gl[w * 4 + 3];
            const int b = 9 - w;
            const int d = 1 << b;
            const bool hi = (lane >> b) & 1;
            const float2 gS = hi ? g11 : g00;
            const float2 gP = hi ? g10 : g01;
#pragma unroll
            for (int i = 0; i < 4; i++) {
                pc2 P;
                P.x = __shfl_xor_sync(0xffffffffu, (unsigned long long)S[i].x, d);
                P.y = __shfl_xor_sync(0xffffffffu, (unsigned long long)S[i].y, d);
                S[i] = pcfma(gP, P, pcmul(gS, S[i]));
            }
        }
    }
    // U[j,k] = conj(v[k]) -> B'[2j][k] = v.x, B'[2j+1][k] = -v.y
    __half* rowR = g_Bb + (size_t)(2 * col) * KBIG;
    __half* rowI = rowR + KBIG;
#pragma unroll
    for (int i = 0; i < 4; i++) {
        float x0, x1, y0, y1;
        upk2(x0, x1, S[i].x); upk2(y0, y1, S[i].y);
        rowR[tc + (2 * i) * 128]     = __float2half_rn(x0);
        rowR[tc + (2 * i + 1) * 128] = __float2half_rn(x1);
        rowI[tc + (2 * i) * 128]     = __float2half_rn(-y0);
        rowI[tc + (2 * i + 1) * 128] = __float2half_rn(-y1);
    }
}

// ---------------- kernel: mma.sync fp16 GEMM + epilogue ----------------
#define STAGE_BYTES 32768
#define GEMM_SMEM   (3 * STAGE_BYTES)   // 98304

__device__ __forceinline__ void load_tile(uint32_t sbase, int stage, int kt,
                                          const __half* gA,
                                          const __half* gB, int tid) {
    const uint32_t aS = sbase + stage * STAGE_BYTES;
    const uint32_t bS = aS + 16384;
    const int r0 = tid >> 3;
    const int c  = tid & 7;
    const uint32_t cx = (uint32_t)(c * 16);
#pragma unroll
    for (int p = 0; p < 4; p++) {
        const int row = p * 32 + r0;
        const uint32_t off = (uint32_t)(row * 128) + (cx ^ ((row & 7) * 16));
        cp_async16(aS + off, gA + (size_t)row * KBIG + (size_t)kt * BKT + c * 8);
    }
#pragma unroll
    for (int p = 0; p < 4; p++) {
        const int row = p * 32 + r0;
        const uint32_t off = (uint32_t)(row * 128) + (cx ^ ((row & 7) * 16));
        cp_async16(bS + off, gB + (size_t)row * KBIG + (size_t)kt * BKT + c * 8);
    }
}

__global__ __launch_bounds__(256, 2) void k_gemm(float* __restrict__ out) {
    extern __shared__ char smem[];
    const uint32_t sbase = smem_u32(smem);
    const int tid = threadIdx.x;
    const int wid = tid >> 5, lane = tid & 31;
    const int wm = wid & 1, wn = wid >> 1;      // 2 x 4 warp grid
    const int m0 = blockIdx.x * 128;
    const int n0 = blockIdx.y * 128;

    const __half* gA = g_As + (size_t)m0 * KBIG;
    const __half* gB = g_Bb + (size_t)n0 * KBIG;

    float acc[4][4][4];
#pragma unroll
    for (int i = 0; i < 4; i++)
#pragma unroll
        for (int j = 0; j < 4; j++)
#pragma unroll
            for (int q = 0; q < 4; q++) acc[i][j][q] = 0.f;

    load_tile(sbase, 0, 0, gA, gB, tid); CP_COMMIT();
    load_tile(sbase, 1, 1, gA, gB, tid); CP_COMMIT();

    const int a_row = wm * 64 + (lane & 7) + ((lane >> 3) & 1) * 8;
    const uint32_t a_kx = ((lane >> 4) & 1) * 16;
    const int b_row = wn * 32 + (lane & 7) + ((lane >> 4) & 1) * 8;
    const uint32_t b_kx = ((lane >> 3) & 1) * 16;

    for (int kt = 0; kt < NKT; kt++) {
        CP_WAIT1();
        __syncthreads();
        if (kt + 2 < NKT) load_tile(sbase, (kt + 2) % 3, kt + 2, gA, gB, tid);
        CP_COMMIT();

        const uint32_t aS = sbase + (kt % 3) * STAGE_BYTES;
        const uint32_t bS = aS + 16384;
#pragma unroll
        for (int ks = 0; ks < 4; ks++) {
            uint32_t afr[4][4], bfr[2][4];
#pragma unroll
            for (int mf = 0; mf < 4; mf++) {
                const int row = a_row + mf * 16;
                const uint32_t kb = (uint32_t)(ks * 32) + a_kx;
                ldsm_x4(afr[mf], aS + (uint32_t)(row * 128) + (kb ^ ((row & 7) * 16)));
            }
#pragma unroll
            for (int nf2 = 0; nf2 < 2; nf2++) {
                const int row = b_row + nf2 * 16;
                const uint32_t kb = (uint32_t)(ks * 32) + b_kx;
                ldsm_x4(bfr[nf2], bS + (uint32_t)(row * 128) + (kb ^ ((row & 7) * 16)));
            }
#pragma unroll
            for (int mf = 0; mf < 4; mf++)
#pragma unroll
                for (int nf = 0; nf < 4; nf++)
                    mma16816(acc[mf][nf], afr[mf], &bfr[nf >> 1][(nf & 1) * 2]);
        }
    }

    const int jbase = (n0 >> 1) + wn * 16;
    const int rbase = m0 + wm * 64 + (lane >> 2);
    const int jq = lane & 3;
#pragma unroll
    for (int mf = 0; mf < 4; mf++) {
#pragma unroll
        for (int nf = 0; nf < 4; nf++) {
            const int j = jbase + nf * 4 + jq;
            if (j < PIX) {
                const float re0 = acc[mf][nf][0], im0 = acc[mf][nf][1];
                const float re1 = acc[mf][nf][2], im1 = acc[mf][nf][3];
                out[(size_t)(rbase + mf * 16) * PIX + j] =
                    fminf((re0 * re0 + im0 * im0) * (float)PIX, 1.0f);
                out[(size_t)(rbase + mf * 16 + 8) * PIX + j] =
                    fminf((re1 * re1 + im1 * im1) * (float)PIX, 1.0f);
            }
        }
    }
}

// ---------------- launch ----------------
extern "C" void kernel_launch(void* const* d_in, const int* in_sizes, int n_in,
                              void* d_out, int out_size) {
    const float* x  = (const float*)d_in[0];
    const float* W  = (const float*)d_in[1];
    const float* b  = (const float*)d_in[2];
    const float* qw = (const float*)d_in[3];
    float* out = (float*)d_out;

    cudaFuncSetAttribute(k_gemm, cudaFuncAttributeMaxDynamicSharedMemorySize, GEMM_SMEM);
    cudaFuncSetAttribute(k_buildU, cudaFuncAttributeMaxDynamicSharedMemorySize, BUILD_SMEM);

    k_gates<<<1, 256>>>(qw);                        // launch 1
    k_angA<<<BATCH / 8, 256>>>(x, W, b);            // launch 2
    k_buildU<<<NJ, 128, BUILD_SMEM>>>();            // launch 3 (832 blocks)
    dim3 gg(BATCH / 128, NBIG / 128);               // 64 x 13
    k_gemm<<<gg, 256, GEMM_SMEM>>>(out);            // launch 4 (profiled)
}

// round 17
// speedup vs baseline: 1.7763x; 1.0070x over previous
#include <cuda_runtime.h>
#include <cuda_fp16.h>
#include <math.h>
#include <stdint.h>

#define BATCH 8192
#define PIX 784
#define WIRES 10
#define DIM 1024
#define QDEPTH 20
#define NGATES (QDEPTH * WIRES)   // 200

#define KBIG 1024                 // pure fp16: A=fp16(S), B=fp16(U)
#define NBIG 1664                 // 832 j-slots x (re,im) interleaved
#define BKT  64                   // K per smem tile
#define NKT  (KBIG / BKT)         // 16

#define NCOLS 784                 // buildU columns actually needed (j < PIX)
#define ANG_BLOCKS (BATCH / 4)    // 2048 blocks x 4 warps = 8192 rows

// ---------------- scratch ----------------
__device__ float2 g_gates[NGATES * 4];          // ADJOINT Rot gates
__device__ __half g_As[(size_t)BATCH * KBIG];   // A' [m][k]
__device__ __half g_Bb[(size_t)NBIG * KBIG];    // GEMM B: [n][k] (rows >=1568 stay 0)

// ---------------- helpers ----------------
__device__ __forceinline__ uint32_t smem_u32(const void* p) {
    uint32_t a;
    asm("{ .reg .u64 t; cvta.to.shared.u64 t, %1; cvt.u32.u64 %0, t; }" : "=r"(a) : "l"(p));
    return a;
}
__device__ __forceinline__ void cp_async16(uint32_t dst, const void* src) {
    asm volatile("cp.async.cg.shared.global [%0], [%1], 16;" :: "r"(dst), "l"(src));
}
#define CP_COMMIT() asm volatile("cp.async.commit_group;" ::: "memory")
#define CP_WAIT1()  asm volatile("cp.async.wait_group 1;" ::: "memory")

__device__ __forceinline__ void ldsm_x4(uint32_t* r, uint32_t addr) {
    asm volatile("ldmatrix.sync.aligned.m8n8.x4.shared.b16 {%0,%1,%2,%3}, [%4];"
                 : "=r"(r[0]), "=r"(r[1]), "=r"(r[2]), "=r"(r[3]) : "r"(addr));
}
__device__ __forceinline__ void mma16816(float* d, const uint32_t* a, const uint32_t* b) {
    asm volatile(
        "mma.sync.aligned.m16n8k16.row.col.f32.f16.f16.f32 "
        "{%0,%1,%2,%3}, {%4,%5,%6,%7}, {%8,%9}, {%0,%1,%2,%3};"
        : "+f"(d[0]), "+f"(d[1]), "+f"(d[2]), "+f"(d[3])
        : "r"(a[0]), "r"(a[1]), "r"(a[2]), "r"(a[3]), "r"(b[0]), "r"(b[1]));
}
__device__ __forceinline__ float2 cmul(float2 g, float2 v) {
    return make_float2(g.x * v.x - g.y * v.y, g.x * v.y + g.y * v.x);
}
__device__ __forceinline__ float2 cadd(float2 a, float2 b) {
    return make_float2(a.x + b.x, a.y + b.y);
}

// ---- packed f32x2 helpers (sm_100 base ISA) ----
__device__ __forceinline__ uint64_t bc2(float v) {
    uint64_t r; asm("mov.b64 %0, {%1, %1};" : "=l"(r) : "f"(v)); return r;
}
__device__ __forceinline__ uint64_t pk2(float lo, float hi) {
    uint64_t r; asm("mov.b64 %0, {%1, %2};" : "=l"(r) : "f"(lo), "f"(hi)); return r;
}
__device__ __forceinline__ void upk2(float& lo, float& hi, uint64_t v) {
    asm("mov.b64 {%0, %1}, %2;" : "=f"(lo), "=f"(hi) : "l"(v));
}
__device__ __forceinline__ uint64_t f2fma(uint64_t a, uint64_t b, uint64_t c) {
    uint64_t d; asm("fma.rn.f32x2 %0, %1, %2, %3;" : "=l"(d) : "l"(a), "l"(b), "l"(c));
    return d;
}
__device__ __forceinline__ uint64_t f2mul(uint64_t a, uint64_t b) {
    uint64_t d; asm("mul.rn.f32x2 %0, %1, %2;" : "=l"(d) : "l"(a), "l"(b));
    return d;
}
struct __align__(16) pc2 { uint64_t x, y; };
__device__ __forceinline__ pc2 pcmul(float2 g, pc2 a) {
    pc2 r;
    r.x = f2fma(bc2(-g.y), a.y, f2mul(bc2(g.x), a.x));
    r.y = f2fma(bc2(g.y),  a.x, f2mul(bc2(g.x), a.y));
    return r;
}
__device__ __forceinline__ pc2 pcfma(float2 g, pc2 a, pc2 acc) {
    acc.x = f2fma(bc2(g.x), a.x, f2fma(bc2(-g.y), a.y, acc.x));
    acc.y = f2fma(bc2(g.x), a.y, f2fma(bc2(g.y),  a.x, acc.y));
    return acc;
}

// ---------------- kernel: ADJOINT Rot gates ----------------
__global__ void k_gates(const float* __restrict__ qw) {
    int g = blockIdx.x * blockDim.x + threadIdx.x;
    if (g >= NGATES) return;
    float phi = qw[g * 3 + 0], th = qw[g * 3 + 1], om = qw[g * 3 + 2];
    float c = cosf(0.5f * th), s = sinf(0.5f * th);
    float A = 0.5f * (phi + om), B = 0.5f * (phi - om);
    float cA = cosf(A), sA = sinf(A), cB = cosf(B), sB = sinf(B);
    g_gates[g * 4 + 0] = make_float2(cA * c,  sA * c);    // conj(m00)
    g_gates[g * 4 + 1] = make_float2(cB * s,  sB * s);    // conj(m10)
    g_gates[g * 4 + 2] = make_float2(-cB * s, sB * s);    // conj(m01)
    g_gates[g * 4 + 3] = make_float2(cA * c, -sA * c);    // conj(m11)
}

// ---------------- device fn: angA for one batch row (one warp) ----------------
__device__ __forceinline__ void angA_row(const float* __restrict__ x,
                                         const float* __restrict__ W,
                                         const float* __restrict__ bias,
                                         int row, int lane) {
    const float4* xr4 = (const float4*)(x + (size_t)row * PIX);
    float acc[WIRES];
#pragma unroll
    for (int w = 0; w < WIRES; w++) acc[w] = 0.f;
    for (int p4 = lane; p4 < PIX / 4; p4 += 32) {
        const float4 xv = xr4[p4];
#pragma unroll
        for (int w = 0; w < WIRES; w++) {
            const float4 wv = __ldg((const float4*)(W + w * PIX) + p4);
            acc[w] = fmaf(xv.x, wv.x, acc[w]);
            acc[w] = fmaf(xv.y, wv.y, acc[w]);
            acc[w] = fmaf(xv.z, wv.z, acc[w]);
            acc[w] = fmaf(xv.w, wv.w, acc[w]);
        }
    }
#pragma unroll
    for (int w = 0; w < WIRES; w++) {
#pragma unroll
        for (int o = 16; o; o >>= 1)
            acc[w] += __shfl_xor_sync(0xffffffffu, acc[w], o);
    }
    float cl = 1.f, cr = 1.f;
#pragma unroll
    for (int w = 0; w < 5; w++) {
        float h = 0.5f * (acc[w] + __ldg(&bias[w]));
        float s, c; sincosf(h, &s, &c);
        cl *= ((lane >> (4 - w)) & 1) ? s : c;
    }
#pragma unroll
    for (int w = 5; w < 10; w++) {
        float h = 0.5f * (acc[w] + __ldg(&bias[w]));
        float s, c; sincosf(h, &s, &c);
        cr *= ((lane >> (9 - w)) & 1) ? s : c;
    }
    char* rowb = (char*)(g_As + (size_t)row * KBIG) + lane * 64;
#pragma unroll
    for (int q = 0; q < 32; q += 8) {
        uint32_t u[4];
#pragma unroll
        for (int j = 0; j < 4; j++) {
            float r0 = __shfl_sync(0xffffffffu, cr, q + 2 * j);
            float r1 = __shfl_sync(0xffffffffu, cr, q + 2 * j + 1);
            __half2 h2 = __floats2half2_rn(cl * r0, cl * r1);
            u[j] = *(uint32_t*)&h2;
        }
        *(uint4*)(rowb + q * 2) = make_uint4(u[0], u[1], u[2], u[3]);
    }
}

// ---------------- fused kernel: buildU (blocks 0..783) + angA (rest) ---------
// buildU: inverse circuit on basis state |col>, packed f32x2 state, 8 amps/thr.
#define BUILD_SMEM (2 * 512 * 16)   // 16384 bytes dynamic

__global__ __launch_bounds__(128, 8) void k_fused(const float* __restrict__ x,
                                                  const float* __restrict__ W,
                                                  const float* __restrict__ bias) {
    extern __shared__ char draw[];
    const int blk = blockIdx.x;

    if (blk >= NCOLS) {
        // ---- angA path: 4 warps, 4 batch rows ----
        const int row = (blk - NCOLS) * 4 + (threadIdx.x >> 5);
        angA_row(x, W, bias, row, threadIdx.x & 31);
        return;
    }

    // ---- buildU path ----
    __shared__ float2 gs[NGATES * 4];
    __shared__ int sigt[9][3];
    const int tc = threadIdx.x;
    const int lane = tc & 31;
    const int col = blk;

    for (int i = tc; i < NGATES * 4; i += 128) gs[i] = g_gates[i];
    if (tc < 27) {
        int r = tc / 3 + 1, bsel = tc % 3;
        int p = 128 << bsel;
#pragma unroll
        for (int w = 0; w <= 9; w++) {          // ASCENDING = inverse ring
            int cm = 1 << (9 - w);
            int tm = 1 << (9 - ((w + r) % 10));
            if (p & cm) p ^= tm;
        }
        sigt[tc / 3][bsel] = p;
    }
    pc2 S[4];
#pragma unroll
    for (int i = 0; i < 4; i++) {
        S[i].x = pk2((tc + (2 * i) * 128) == col ? 1.f : 0.f,
                     (tc + (2 * i + 1) * 128) == col ? 1.f : 0.f);
        S[i].y = bc2(0.f);
    }
    __syncthreads();

    int pb = 0;
    for (int ll = 0; ll < QDEPTH; ll++) {
        const int l = QDEPTH - 1 - ll;
        const float2* gl = &gs[l * WIRES * 4];

        // ---- inverse CNOT ring ----
        {
            const int ri = l % 9;
            const int r = ri + 1;
            float2* base = (float2*)draw + pb * 1024;
#pragma unroll
            for (int i = 0; i < 4; i++) {
                float x0, x1, y0, y1;
                upk2(x0, x1, S[i].x); upk2(y0, y1, S[i].y);
                base[tc + (2 * i) * 128]     = make_float2(x0, y0);
                base[tc + (2 * i + 1) * 128] = make_float2(x1, y1);
            }
            __syncthreads();
            int st = tc;
#pragma unroll
            for (int w = 0; w <= 9; w++) {
                int cm = 1 << (9 - w);
                int tm = 1 << (9 - ((w + r) % 10));
                if (st & cm) st ^= tm;
            }
            const int s7 = sigt[ri][0], s8 = sigt[ri][1], s9 = sigt[ri][2];
            float2 gval[8];
#pragma unroll
            for (int q = 0; q < 8; q++) {
                int idx = st ^ ((q & 1) ? s7 : 0) ^ ((q & 2) ? s8 : 0) ^ ((q & 4) ? s9 : 0);
                gval[q] = base[idx];
            }
#pragma unroll
            for (int i = 0; i < 4; i++) {
                S[i].x = pk2(gval[2 * i].x, gval[2 * i + 1].x);
                S[i].y = pk2(gval[2 * i].y, gval[2 * i + 1].y);
            }
            pb ^= 1;
        }

        // ---- wire 0 (pair-idx bit 1) ----
        {
            const float2 g00 = gl[0], g01 = gl[1], g10 = gl[2], g11 = gl[3];
#pragma unroll
            for (int i = 0; i < 2; i++) {
                pc2 a0 = S[i], a1 = S[i + 2];
                S[i]     = pcfma(g01, a1, pcmul(g00, a0));
                S[i + 2] = pcfma(g11, a1, pcmul(g10, a0));
            }
        }
        // ---- wire 1 (pair-idx bit 0) ----
        {
            const float2 g00 = gl[4], g01 = gl[5], g10 = gl[6], g11 = gl[7];
#pragma unroll
            for (int i = 0; i < 4; i += 2) {
                pc2 a0 = S[i], a1 = S[i + 1];
                S[i]     = pcfma(g01, a1, pcmul(g00, a0));
                S[i + 1] = pcfma(g11, a1, pcmul(g10, a0));
            }
        }
        // ---- wire 2 (packed lane): scalar ----
        {
            const float2 g00 = gl[8], g01 = gl[9], g10 = gl[10], g11 = gl[11];
#pragma unroll
            for (int i = 0; i < 4; i++) {
                float x0, x1, y0, y1;
                upk2(x0, x1, S[i].x); upk2(y0, y1, S[i].y);
                float2 a0 = make_float2(x0, y0), a1 = make_float2(x1, y1);
                float2 n0 = cadd(cmul(g00, a0), cmul(g01, a1));
                float2 n1 = cadd(cmul(g10, a0), cmul(g11, a1));
                S[i].x = pk2(n0.x, n1.x); S[i].y = pk2(n0.y, n1.y);
            }
        }
        // ---- wires 3,4 (tc bits 6,5): smem exchange ----
#pragma unroll
        for (int w = 3; w <= 4; w++) {
            const float2 g00 = gl[w * 4], g01 = gl[w * 4 + 1];
            const float2 g10 = gl[w * 4 + 2], g11 = gl[w * 4 + 3];
            const int b = 9 - w;
            const int d = 1 << b;
            pc2* pp = (pc2*)draw + pb * 512;
#pragma unroll
            for (int i = 0; i < 4; i++) pp[i * 128 + tc] = S[i];
            __syncthreads();
            const int pt = tc ^ d;
            const bool hi = (tc >> b) & 1;
            const float2 gS = hi ? g11 : g00;
            const float2 gP = hi ? g10 : g01;
#pragma unroll
            for (int i = 0; i < 4; i++) {
                pc2 P = pp[i * 128 + pt];
                S[i] = pcfma(gP, P, pcmul(gS, S[i]));
            }
            pb ^= 1;
        }
        // ---- wires 5..9 (lane bits): shfl ----
#pragma unroll
        for (int w = 5; w <= 9; w++) {
            const float2 g00 = gl[w * 4], g01 = gl[w * 4 + 1];
            const float2 g10 = gl[w * 4 + 2], g11 = gl[w * 4 + 3];
            const int b = 9 - w;
            const int d = 1 << b;
            const bool hi = (lane >> b) & 1;
            const float2 gS = hi ? g11 : g00;
            const float2 gP = hi ? g10 : g01;
#pragma unroll
            for (int i = 0; i < 4; i++) {
                pc2 P;
                P.x = __shfl_xor_sync(0xffffffffu, (unsigned long long)S[i].x, d);
                P.y = __shfl_xor_sync(0xffffffffu, (unsigned long long)S[i].y, d);
                S[i] = pcfma(gP, P, pcmul(gS, S[i]));
            }
        }
    }
    // U[j,k] = conj(v[k]) -> B'[2j][k] = v.x, B'[2j+1][k] = -v.y
    __half* rowR = g_Bb + (size_t)(2 * col) * KBIG;
    __half* rowI = rowR + KBIG;
#pragma unroll
    for (int i = 0; i < 4; i++) {
        float x0, x1, y0, y1;
        upk2(x0, x1, S[i].x); upk2(y0, y1, S[i].y);
        rowR[tc + (2 * i) * 128]     = __float2half_rn(x0);
        rowR[tc + (2 * i + 1) * 128] = __float2half_rn(x1);
        rowI[tc + (2 * i) * 128]     = __float2half_rn(-y0);
        rowI[tc + (2 * i + 1) * 128] = __float2half_rn(-y1);
    }
}

// ---------------- kernel: mma.sync fp16 GEMM + epilogue ----------------
#define STAGE_BYTES 32768
#define GEMM_SMEM   (3 * STAGE_BYTES)   // 98304

__device__ __forceinline__ void load_tile(uint32_t sbase, int stage, int kt,
                                          const __half* gA,
                                          const __half* gB, int tid) {
    const uint32_t aS = sbase + stage * STAGE_BYTES;
    const uint32_t bS = aS + 16384;
    const int r0 = tid >> 3;
    const int c  = tid & 7;
    const uint32_t cx = (uint32_t)(c * 16);
#pragma unroll
    for (int p = 0; p < 4; p++) {
        const int row = p * 32 + r0;
        const uint32_t off = (uint32_t)(row * 128) + (cx ^ ((row & 7) * 16));
        cp_async16(aS + off, gA + (size_t)row * KBIG + (size_t)kt * BKT + c * 8);
    }
#pragma unroll
    for (int p = 0; p < 4; p++) {
        const int row = p * 32 + r0;
        const uint32_t off = (uint32_t)(row * 128) + (cx ^ ((row & 7) * 16));
        cp_async16(bS + off, gB + (size_t)row * KBIG + (size_t)kt * BKT + c * 8);
    }
}

__global__ __launch_bounds__(256, 2) void k_gemm(float* __restrict__ out) {
    extern __shared__ char smem[];
    const uint32_t sbase = smem_u32(smem);
    const int tid = threadIdx.x;
    const int wid = tid >> 5, lane = tid & 31;
    const int wm = wid & 1, wn = wid >> 1;      // 2 x 4 warp grid
    const int m0 = blockIdx.x * 128;
    const int n0 = blockIdx.y * 128;

    const __half* gA = g_As + (size_t)m0 * KBIG;
    const __half* gB = g_Bb + (size_t)n0 * KBIG;

    float acc[4][4][4];
#pragma unroll
    for (int i = 0; i < 4; i++)
#pragma unroll
        for (int j = 0; j < 4; j++)
#pragma unroll
            for (int q = 0; q < 4; q++) acc[i][j][q] = 0.f;

    load_tile(sbase, 0, 0, gA, gB, tid); CP_COMMIT();
    load_tile(sbase, 1, 1, gA, gB, tid); CP_COMMIT();

    const int a_row = wm * 64 + (lane & 7) + ((lane >> 3) & 1) * 8;
    const uint32_t a_kx = ((lane >> 4) & 1) * 16;
    const int b_row = wn * 32 + (lane & 7) + ((lane >> 4) & 1) * 8;
    const uint32_t b_kx = ((lane >> 3) & 1) * 16;

    for (int kt = 0; kt < NKT; kt++) {
        CP_WAIT1();
        __syncthreads();
        if (kt + 2 < NKT) load_tile(sbase, (kt + 2) % 3, kt + 2, gA, gB, tid);
        CP_COMMIT();

        const uint32_t aS = sbase + (kt % 3) * STAGE_BYTES;
        const uint32_t bS = aS + 16384;
#pragma unroll
        for (int ks = 0; ks < 4; ks++) {
            uint32_t afr[4][4], bfr[2][4];
#pragma unroll
            for (int mf = 0; mf < 4; mf++) {
                const int row = a_row + mf * 16;
                const uint32_t kb = (uint32_t)(ks * 32) + a_kx;
                ldsm_x4(afr[mf], aS + (uint32_t)(row * 128) + (kb ^ ((row & 7) * 16)));
            }
#pragma unroll
            for (int nf2 = 0; nf2 < 2; nf2++) {
                const int row = b_row + nf2 * 16;
                const uint32_t kb = (uint32_t)(ks * 32) + b_kx;
                ldsm_x4(bfr[nf2], bS + (uint32_t)(row * 128) + (kb ^ ((row & 7) * 16)));
            }
#pragma unroll
            for (int mf = 0; mf < 4; mf++)
#pragma unroll
                for (int nf = 0; nf < 4; nf++)
                    mma16816(acc[mf][nf], afr[mf], &bfr[nf >> 1][(nf & 1) * 2]);
        }
    }

    const int jbase = (n0 >> 1) + wn * 16;
    const int rbase = m0 + wm * 64 + (lane >> 2);
    const int jq = lane & 3;
#pragma unroll
    for (int mf = 0; mf < 4; mf++) {
#pragma unroll
        for (int nf = 0; nf < 4; nf++) {
            const int j = jbase + nf * 4 + jq;
            if (j < PIX) {
                const float re0 = acc[mf][nf][0], im0 = acc[mf][nf][1];
                const float re1 = acc[mf][nf][2], im1 = acc[mf][nf][3];
                out[(size_t)(rbase + mf * 16) * PIX + j] =
                    fminf((re0 * re0 + im0 * im0) * (float)PIX, 1.0f);
                out[(size_t)(rbase + mf * 16 + 8) * PIX + j] =
                    fminf((re1 * re1 + im1 * im1) * (float)PIX, 1.0f);
            }
        }
    }
}

// ---------------- launch ----------------
extern "C" void kernel_launch(void* const* d_in, const int* in_sizes, int n_in,
                              void* d_out, int out_size) {
    const float* x  = (const float*)d_in[0];
    const float* W  = (const float*)d_in[1];
    const float* b  = (const float*)d_in[2];
    const float* qw = (const float*)d_in[3];
    float* out = (float*)d_out;

    cudaFuncSetAttribute(k_gemm, cudaFuncAttributeMaxDynamicSharedMemorySize, GEMM_SMEM);
    cudaFuncSetAttribute(k_fused, cudaFuncAttributeMaxDynamicSharedMemorySize, BUILD_SMEM);

    k_gates<<<1, 256>>>(qw);                               // launch 1
    k_fused<<<NCOLS + ANG_BLOCKS, 128, BUILD_SMEM>>>(x, W, b);  // launch 2 (2832 blocks)
    dim3 gg(BATCH / 128, NBIG / 128);                      // 64 x 13
    k_gemm<<<gg, 256, GEMM_SMEM>>>(out);                   // launch 3
}